// round 1
// baseline (speedup 1.0000x reference)
#include <cuda_runtime.h>
#include <cstdint>

#define RS 256
#define NV 2048
#define NF 4096
#define IMGH 480
#define IMGW 640
#define NPIX (IMGH * IMGW)
#define NBLK (NPIX / 256)
#define CHUNK_F 128

__device__ float2 g_xy[NV];
__device__ float4 g_face[NF * 3];
__device__ float  g_si[RS * RS];
__device__ float  g_partial[NBLK];

// ---------------------------------------------------------------------------
// Kernel 1: se3_exp + vertex transform + projection (tiny)
// ---------------------------------------------------------------------------
__global__ void setup_kernel(const float* __restrict__ dof,
                             const float* __restrict__ verts,
                             const float* __restrict__ Kin) {
    __shared__ float sR[9], sT[3], sK[9];
    int tid = threadIdx.x;
    if (tid == 0) {
        float v0 = dof[0], v1 = dof[1], v2 = dof[2];
        float w0 = dof[3], w1 = dof[4], w2 = dof[5];
        float th2 = w0 * w0 + w1 * w1 + w2 * w2;
        float th  = sqrtf(th2 + 1e-30f);
        bool small = th < 1e-4f;
        float th_s  = small ? 1.f : th;
        float th2_s = small ? 1.f : th2;
        float A = small ? (1.f - th2 / 6.f)   : (sinf(th_s) / th_s);
        float B = small ? (0.5f - th2 / 24.f) : ((1.f - cosf(th_s)) / th2_s);
        float C = small ? (1.f / 6.f - th2 / 120.f)
                        : ((th_s - sinf(th_s)) / (th2_s * th_s));
        float Kx[9] = {0.f, -w2,  w1,
                       w2,  0.f, -w0,
                      -w1,  w0,  0.f};
        float K2[9];
        #pragma unroll
        for (int r = 0; r < 3; r++)
            #pragma unroll
            for (int c = 0; c < 3; c++) {
                float acc = 0.f;
                #pragma unroll
                for (int k = 0; k < 3; k++) acc += Kx[r * 3 + k] * Kx[k * 3 + c];
                K2[r * 3 + c] = acc;
            }
        float V[9];
        #pragma unroll
        for (int i = 0; i < 9; i++) {
            float I = (i == 0 || i == 4 || i == 8) ? 1.f : 0.f;
            sR[i] = I + A * Kx[i] + B * K2[i];
            V[i]  = I + B * Kx[i] + C * K2[i];
        }
        sT[0] = V[0] * v0 + V[1] * v1 + V[2] * v2;
        sT[1] = V[3] * v0 + V[4] * v1 + V[5] * v2;
        sT[2] = V[6] * v0 + V[7] * v1 + V[8] * v2;
    }
    if (tid < 9) sK[tid] = Kin[tid];
    __syncthreads();
    for (int i = tid; i < NV; i += blockDim.x) {
        float x = verts[3 * i + 0], y = verts[3 * i + 1], z = verts[3 * i + 2];
        float cx = sR[0] * x + sR[1] * y + sR[2] * z + sT[0];
        float cy = sR[3] * x + sR[4] * y + sR[5] * z + sT[1];
        float cz = sR[6] * x + sR[7] * y + sR[8] * z + sT[2];
        float u = sK[0] * cx + sK[1] * cy + sK[2] * cz;
        float v = sK[3] * cx + sK[4] * cy + sK[5] * cz;
        float w = sK[6] * cx + sK[7] * cy + sK[8] * cz;
        g_xy[i] = make_float2((u / w) * 0.4f, (v / w) * 0.4f);
    }
}

// ---------------------------------------------------------------------------
// Kernel 2: per-face edge coefficients  d_k = P_k*px + Q_k*py + C_k
// (sign and 1/elen folded in)
// ---------------------------------------------------------------------------
__global__ void face_kernel(const int* __restrict__ faces) {
    int f = blockIdx.x * blockDim.x + threadIdx.x;
    if (f >= NF) return;
    int i0 = faces[3 * f + 0];
    int i1 = faces[3 * f + 1];
    int i2 = faces[3 * f + 2];
    float2 p0 = g_xy[i0], p1 = g_xy[i1], p2 = g_xy[i2];
    float2 e[3];
    e[0] = make_float2(p1.x - p0.x, p1.y - p0.y);
    e[1] = make_float2(p2.x - p1.x, p2.y - p1.y);
    e[2] = make_float2(p0.x - p2.x, p0.y - p2.y);
    float2 a[3] = {p0, p1, p2};
    // area2 = cross2(e0, -e2)
    float area2 = e[0].y * e[2].x - e[0].x * e[2].y;
    float sgn = (area2 >= 0.f) ? 1.f : -1.f;
    #pragma unroll
    for (int k = 0; k < 3; k++) {
        float elen = sqrtf(e[k].x * e[k].x + e[k].y * e[k].y) + 1e-9f;
        float s = sgn / elen;
        float c0 = e[k].x * a[k].y - e[k].y * a[k].x;
        // d = s*(e.x*py - e.y*px - c0)  ->  P*px + Q*py + C
        g_face[f * 3 + k] = make_float4(-s * e[k].y, s * e[k].x, -s * c0, 0.f);
    }
}

// ---------------------------------------------------------------------------
// Kernel 3: rasterizer. One thread = one render pixel.
// prod = Π max(sigmoid(-2*dmin), 1e-6) ; si = 1 - prod
// Warp-coherent skip when all lanes have dmin < -30 (factor == 1.0 exactly,
// and contributes 0 to the reference's fp32 logp as well).
// ---------------------------------------------------------------------------
__global__ __launch_bounds__(256) void raster_kernel() {
    __shared__ float4 sf[CHUNK_F * 3];
    int tid  = threadIdx.x;
    int warp = tid >> 5, lane = tid & 31;
    // 16x16 CTA tile; warp covers an 8x4 pixel sub-tile (spatially coherent)
    int bx = blockIdx.x & 15, by = blockIdx.x >> 4;
    int wx = warp & 1, wy = warp >> 1;
    int x = bx * 16 + wx * 8 + (lane & 7);
    int y = by * 16 + wy * 4 + (lane >> 3);
    float px = (float)x + 0.5f;
    float py = (float)y + 0.5f;

    float prod = 1.f;
    const float KEXP = 2.8853900817779268f;  // 2 * log2(e)

    for (int base = 0; base < NF; base += CHUNK_F) {
        __syncthreads();
        #pragma unroll
        for (int i = tid; i < CHUNK_F * 3; i += 256)
            sf[i] = g_face[base * 3 + i];
        __syncthreads();

        #pragma unroll 4
        for (int f = 0; f < CHUNK_F; f++) {
            float4 E0 = sf[f * 3 + 0];
            float4 E1 = sf[f * 3 + 1];
            float4 E2 = sf[f * 3 + 2];
            float d0 = fmaf(E0.y, py, fmaf(E0.x, px, E0.z));
            float d1 = fmaf(E1.y, py, fmaf(E1.x, px, E1.z));
            float d2 = fmaf(E2.y, py, fmaf(E2.x, px, E2.z));
            float dmin = fminf(d0, fminf(d1, d2));
            if (__any_sync(0xffffffffu, dmin > -30.f)) {
                float t, r;
                asm("ex2.approx.ftz.f32 %0, %1;" : "=f"(t) : "f"(dmin * KEXP));
                float den = 1.f + t;
                asm("rcp.approx.ftz.f32 %0, %1;" : "=f"(r) : "f"(den));
                prod *= fmaxf(r, 1e-6f);
            }
        }
    }
    g_si[y * RS + x] = 1.f - prod;
}

// ---------------------------------------------------------------------------
// Kernel 4: nearest upsample 256->640, crop 480x640, write si, partial SSE
// nearest index: floor((i+0.5)*256/640) == (2i+1)/5 (exact integer form)
// ---------------------------------------------------------------------------
__global__ __launch_bounds__(256) void finalize_kernel(const float* __restrict__ mask,
                                                       float* __restrict__ out,
                                                       int si_offset) {
    int idx = blockIdx.x * 256 + threadIdx.x;
    int r = idx / IMGW;
    int c = idx - r * IMGW;
    int sr = (2 * r + 1) / 5;
    int sc = (2 * c + 1) / 5;
    float si = g_si[sr * RS + sc];
    out[idx + si_offset] = si;
    float d = si - mask[idx];
    float sq = d * d;

    // deterministic block reduction
    __shared__ float red[8];
    #pragma unroll
    for (int o = 16; o > 0; o >>= 1)
        sq += __shfl_down_sync(0xffffffffu, sq, o);
    int warp = threadIdx.x >> 5, lane = threadIdx.x & 31;
    if (lane == 0) red[warp] = sq;
    __syncthreads();
    if (threadIdx.x == 0) {
        float s = 0.f;
        #pragma unroll
        for (int w = 0; w < 8; w++) s += red[w];
        g_partial[blockIdx.x] = s;
    }
}

__global__ __launch_bounds__(256) void loss_kernel(float* __restrict__ out) {
    int tid = threadIdx.x;
    float s = 0.f;
    for (int i = tid; i < NBLK; i += 256) s += g_partial[i];
    __shared__ float red[256];
    red[tid] = s;
    __syncthreads();
    #pragma unroll
    for (int o = 128; o > 0; o >>= 1) {
        if (tid < o) red[tid] += red[tid + o];
        __syncthreads();
    }
    if (tid == 0) out[0] = red[0];
}

// ---------------------------------------------------------------------------
extern "C" void kernel_launch(void* const* d_in, const int* in_sizes, int n_in,
                              void* d_out, int out_size) {
    const float* dof   = (const float*)d_in[0];
    const float* verts = (const float*)d_in[1];
    const int*   faces = (const int*)d_in[2];
    const float* K     = (const float*)d_in[3];
    const float* mask  = (const float*)d_in[4];
    float* out = (float*)d_out;

    int has_loss = (out_size >= NPIX + 1) ? 1 : 0;

    setup_kernel<<<1, 256>>>(dof, verts, K);
    face_kernel<<<NF / 256, 256>>>(faces);
    raster_kernel<<<256, 256>>>();
    finalize_kernel<<<NBLK, 256>>>(mask, out, has_loss);
    if (has_loss) loss_kernel<<<1, 256>>>(out);
}

// round 2
// speedup vs baseline: 1.3227x; 1.3227x over previous
#include <cuda_runtime.h>
#include <cstdint>

#define RS 256
#define NV 2048
#define NF 4096
#define IMGH 480
#define IMGW 640
#define NPIX (IMGH * IMGW)
#define NBLK (NPIX / 256)
#define CHUNK_F 128
#define THRESH (-15.0f)

__device__ float2 g_xy[NV];
__device__ float4 g_face[NF * 3];
__device__ float  g_si[RS * RS];
__device__ float  g_partial[NBLK];

// ---------------------------------------------------------------------------
// Kernel 1: se3_exp + vertex transform + projection (tiny)
// ---------------------------------------------------------------------------
__global__ void setup_kernel(const float* __restrict__ dof,
                             const float* __restrict__ verts,
                             const float* __restrict__ Kin) {
    __shared__ float sR[9], sT[3], sK[9];
    int tid = threadIdx.x;
    if (tid == 0) {
        float v0 = dof[0], v1 = dof[1], v2 = dof[2];
        float w0 = dof[3], w1 = dof[4], w2 = dof[5];
        float th2 = w0 * w0 + w1 * w1 + w2 * w2;
        float th  = sqrtf(th2 + 1e-30f);
        bool small = th < 1e-4f;
        float th_s  = small ? 1.f : th;
        float th2_s = small ? 1.f : th2;
        float A = small ? (1.f - th2 / 6.f)   : (sinf(th_s) / th_s);
        float B = small ? (0.5f - th2 / 24.f) : ((1.f - cosf(th_s)) / th2_s);
        float C = small ? (1.f / 6.f - th2 / 120.f)
                        : ((th_s - sinf(th_s)) / (th2_s * th_s));
        float Kx[9] = {0.f, -w2,  w1,
                       w2,  0.f, -w0,
                      -w1,  w0,  0.f};
        float K2[9];
        #pragma unroll
        for (int r = 0; r < 3; r++)
            #pragma unroll
            for (int c = 0; c < 3; c++) {
                float acc = 0.f;
                #pragma unroll
                for (int k = 0; k < 3; k++) acc += Kx[r * 3 + k] * Kx[k * 3 + c];
                K2[r * 3 + c] = acc;
            }
        float V[9];
        #pragma unroll
        for (int i = 0; i < 9; i++) {
            float I = (i == 0 || i == 4 || i == 8) ? 1.f : 0.f;
            sR[i] = I + A * Kx[i] + B * K2[i];
            V[i]  = I + B * Kx[i] + C * K2[i];
        }
        sT[0] = V[0] * v0 + V[1] * v1 + V[2] * v2;
        sT[1] = V[3] * v0 + V[4] * v1 + V[5] * v2;
        sT[2] = V[6] * v0 + V[7] * v1 + V[8] * v2;
    }
    if (tid < 9) sK[tid] = Kin[tid];
    __syncthreads();
    for (int i = tid; i < NV; i += blockDim.x) {
        float x = verts[3 * i + 0], y = verts[3 * i + 1], z = verts[3 * i + 2];
        float cx = sR[0] * x + sR[1] * y + sR[2] * z + sT[0];
        float cy = sR[3] * x + sR[4] * y + sR[5] * z + sT[1];
        float cz = sR[6] * x + sR[7] * y + sR[8] * z + sT[2];
        float u = sK[0] * cx + sK[1] * cy + sK[2] * cz;
        float v = sK[3] * cx + sK[4] * cy + sK[5] * cz;
        float w = sK[6] * cx + sK[7] * cy + sK[8] * cz;
        g_xy[i] = make_float2((u / w) * 0.4f, (v / w) * 0.4f);
    }
}

// ---------------------------------------------------------------------------
// Kernel 2: per-face edge coefficients  d_k = P_k*px + Q_k*py + C_k
// ---------------------------------------------------------------------------
__global__ void face_kernel(const int* __restrict__ faces) {
    int f = blockIdx.x * blockDim.x + threadIdx.x;
    if (f >= NF) return;
    int i0 = faces[3 * f + 0];
    int i1 = faces[3 * f + 1];
    int i2 = faces[3 * f + 2];
    float2 p0 = g_xy[i0], p1 = g_xy[i1], p2 = g_xy[i2];
    float2 e[3];
    e[0] = make_float2(p1.x - p0.x, p1.y - p0.y);
    e[1] = make_float2(p2.x - p1.x, p2.y - p1.y);
    e[2] = make_float2(p0.x - p2.x, p0.y - p2.y);
    float2 a[3] = {p0, p1, p2};
    float area2 = e[0].y * e[2].x - e[0].x * e[2].y;
    float sgn = (area2 >= 0.f) ? 1.f : -1.f;
    #pragma unroll
    for (int k = 0; k < 3; k++) {
        float elen = sqrtf(e[k].x * e[k].x + e[k].y * e[k].y) + 1e-9f;
        float s = sgn / elen;
        float c0 = e[k].x * a[k].y - e[k].y * a[k].x;
        g_face[f * 3 + k] = make_float4(-s * e[k].y, s * e[k].x, -s * c0, 0.f);
    }
}

// ---------------------------------------------------------------------------
// Kernel 3: rasterizer with per-tile face culling.
// Phase 1: each CTA (16x16 px tile) compacts the faces relevant to its tile
//          (ordered compaction -> ascending face ids -> stable product order).
// Phase 2: rasterize only listed faces, staged through shared in chunks.
// Cull rule: face irrelevant if ANY edge has max_{tile} d_k < THRESH
//            (then dmin < THRESH for every pixel; factor == 1 to fp32).
// ---------------------------------------------------------------------------
__global__ __launch_bounds__(256) void raster_kernel() {
    __shared__ unsigned short slist[NF];
    __shared__ float4 sf[CHUNK_F * 3];
    __shared__ int swarp[8];
    __shared__ int scount;

    int tid  = threadIdx.x;
    int warp = tid >> 5, lane = tid & 31;
    int bx = blockIdx.x & 15, by = blockIdx.x >> 4;

    // tile pixel-center range: [16bx+0.5, 16bx+15.5] -> center 16bx+8, half 7.5
    float tcx = (float)(bx * 16 + 8);
    float tcy = (float)(by * 16 + 8);

    if (tid == 0) scount = 0;
    __syncthreads();

    // ---- Phase 1: ordered compaction of relevant faces ----
    for (int r = 0; r < NF / 256; r++) {
        int f = r * 256 + tid;
        float4 E0 = g_face[f * 3 + 0];
        float4 E1 = g_face[f * 3 + 1];
        float4 E2 = g_face[f * 3 + 2];
        float m0 = fmaf(E0.x, tcx, fmaf(E0.y, tcy, E0.z)) + 7.5f * (fabsf(E0.x) + fabsf(E0.y));
        float m1 = fmaf(E1.x, tcx, fmaf(E1.y, tcy, E1.z)) + 7.5f * (fabsf(E1.x) + fabsf(E1.y));
        float m2 = fmaf(E2.x, tcx, fmaf(E2.y, tcy, E2.z)) + 7.5f * (fabsf(E2.x) + fabsf(E2.y));
        bool keep = (m0 >= THRESH) && (m1 >= THRESH) && (m2 >= THRESH);

        unsigned b = __ballot_sync(0xffffffffu, keep);
        if (lane == 0) swarp[warp] = __popc(b);
        __syncthreads();
        int base = scount;
        #pragma unroll
        for (int w = 0; w < 8; w++) base += (w < warp) ? swarp[w] : 0;
        if (keep)
            slist[base + __popc(b & ((1u << lane) - 1u))] = (unsigned short)f;
        __syncthreads();
        if (tid == 0) {
            int tot = 0;
            #pragma unroll
            for (int w = 0; w < 8; w++) tot += swarp[w];
            scount += tot;
        }
        __syncthreads();
    }
    int nlist = scount;

    // ---- Phase 2: rasterize listed faces ----
    int wx = warp & 1, wy = warp >> 1;
    int x = bx * 16 + wx * 8 + (lane & 7);
    int y = by * 16 + wy * 4 + (lane >> 3);
    float px = (float)x + 0.5f;
    float py = (float)y + 0.5f;

    float prod = 1.f;
    const float KEXP = 2.8853900817779268f;  // 2 * log2(e)

    for (int base = 0; base < nlist; base += CHUNK_F) {
        int n = min(CHUNK_F, nlist - base);
        __syncthreads();
        for (int j = tid; j < n * 3; j += 256) {
            int li = j / 3, k = j - li * 3;
            sf[j] = g_face[(int)slist[base + li] * 3 + k];
        }
        __syncthreads();

        for (int f = 0; f < n; f++) {
            float4 E0 = sf[f * 3 + 0];
            float4 E1 = sf[f * 3 + 1];
            float4 E2 = sf[f * 3 + 2];
            float d0 = fmaf(E0.y, py, fmaf(E0.x, px, E0.z));
            float d1 = fmaf(E1.y, py, fmaf(E1.x, px, E1.z));
            float d2 = fmaf(E2.y, py, fmaf(E2.x, px, E2.z));
            float dmin = fminf(d0, fminf(d1, d2));
            if (__any_sync(0xffffffffu, dmin > THRESH)) {
                float t, rc;
                asm("ex2.approx.ftz.f32 %0, %1;" : "=f"(t) : "f"(dmin * KEXP));
                float den = 1.f + t;
                asm("rcp.approx.ftz.f32 %0, %1;" : "=f"(rc) : "f"(den));
                prod *= fmaxf(rc, 1e-6f);
            }
        }
    }
    g_si[y * RS + x] = 1.f - prod;
}

// ---------------------------------------------------------------------------
// Kernel 4: nearest upsample 256->640, crop, write si, partial SSE
// ---------------------------------------------------------------------------
__global__ __launch_bounds__(256) void finalize_kernel(const float* __restrict__ mask,
                                                       float* __restrict__ out,
                                                       int si_offset) {
    int idx = blockIdx.x * 256 + threadIdx.x;
    int r = idx / IMGW;
    int c = idx - r * IMGW;
    int sr = (2 * r + 1) / 5;
    int sc = (2 * c + 1) / 5;
    float si = g_si[sr * RS + sc];
    out[idx + si_offset] = si;
    float d = si - mask[idx];
    float sq = d * d;

    __shared__ float red[8];
    #pragma unroll
    for (int o = 16; o > 0; o >>= 1)
        sq += __shfl_down_sync(0xffffffffu, sq, o);
    int warp = threadIdx.x >> 5, lane = threadIdx.x & 31;
    if (lane == 0) red[warp] = sq;
    __syncthreads();
    if (threadIdx.x == 0) {
        float s = 0.f;
        #pragma unroll
        for (int w = 0; w < 8; w++) s += red[w];
        g_partial[blockIdx.x] = s;
    }
}

__global__ __launch_bounds__(256) void loss_kernel(float* __restrict__ out) {
    int tid = threadIdx.x;
    float s = 0.f;
    for (int i = tid; i < NBLK; i += 256) s += g_partial[i];
    __shared__ float red[256];
    red[tid] = s;
    __syncthreads();
    #pragma unroll
    for (int o = 128; o > 0; o >>= 1) {
        if (tid < o) red[tid] += red[tid + o];
        __syncthreads();
    }
    if (tid == 0) out[0] = red[0];
}

// ---------------------------------------------------------------------------
extern "C" void kernel_launch(void* const* d_in, const int* in_sizes, int n_in,
                              void* d_out, int out_size) {
    const float* dof   = (const float*)d_in[0];
    const float* verts = (const float*)d_in[1];
    const int*   faces = (const int*)d_in[2];
    const float* K     = (const float*)d_in[3];
    const float* mask  = (const float*)d_in[4];
    float* out = (float*)d_out;

    int has_loss = (out_size >= NPIX + 1) ? 1 : 0;

    setup_kernel<<<1, 256>>>(dof, verts, K);
    face_kernel<<<NF / 256, 256>>>(faces);
    raster_kernel<<<256, 256>>>();
    finalize_kernel<<<NBLK, 256>>>(mask, out, has_loss);
    if (has_loss) loss_kernel<<<1, 256>>>(out);
}

// round 3
// speedup vs baseline: 1.6353x; 1.2364x over previous
#include <cuda_runtime.h>
#include <cstdint>

#define RS 256
#define NV 2048
#define NF 4096
#define IMGH 480
#define IMGW 640
#define NPIX (IMGH * IMGW)
#define NBLK (NPIX / 256)
#define THRESH (-15.0f)

__device__ float2 g_xy[NV];
__device__ float4 g_face[NF * 3];
__device__ float  g_si[RS * RS];
__device__ float  g_partial[NBLK];

// ---------------------------------------------------------------------------
// Kernel 1: se3_exp + vertex transform + projection (tiny)
// ---------------------------------------------------------------------------
__global__ void setup_kernel(const float* __restrict__ dof,
                             const float* __restrict__ verts,
                             const float* __restrict__ Kin) {
    __shared__ float sR[9], sT[3], sK[9];
    int tid = threadIdx.x;
    if (tid == 0) {
        float v0 = dof[0], v1 = dof[1], v2 = dof[2];
        float w0 = dof[3], w1 = dof[4], w2 = dof[5];
        float th2 = w0 * w0 + w1 * w1 + w2 * w2;
        float th  = sqrtf(th2 + 1e-30f);
        bool small = th < 1e-4f;
        float th_s  = small ? 1.f : th;
        float th2_s = small ? 1.f : th2;
        float A = small ? (1.f - th2 / 6.f)   : (sinf(th_s) / th_s);
        float B = small ? (0.5f - th2 / 24.f) : ((1.f - cosf(th_s)) / th2_s);
        float C = small ? (1.f / 6.f - th2 / 120.f)
                        : ((th_s - sinf(th_s)) / (th2_s * th_s));
        float Kx[9] = {0.f, -w2,  w1,
                       w2,  0.f, -w0,
                      -w1,  w0,  0.f};
        float K2[9];
        #pragma unroll
        for (int r = 0; r < 3; r++)
            #pragma unroll
            for (int c = 0; c < 3; c++) {
                float acc = 0.f;
                #pragma unroll
                for (int k = 0; k < 3; k++) acc += Kx[r * 3 + k] * Kx[k * 3 + c];
                K2[r * 3 + c] = acc;
            }
        float V[9];
        #pragma unroll
        for (int i = 0; i < 9; i++) {
            float I = (i == 0 || i == 4 || i == 8) ? 1.f : 0.f;
            sR[i] = I + A * Kx[i] + B * K2[i];
            V[i]  = I + B * Kx[i] + C * K2[i];
        }
        sT[0] = V[0] * v0 + V[1] * v1 + V[2] * v2;
        sT[1] = V[3] * v0 + V[4] * v1 + V[5] * v2;
        sT[2] = V[6] * v0 + V[7] * v1 + V[8] * v2;
    }
    if (tid < 9) sK[tid] = Kin[tid];
    __syncthreads();
    for (int i = tid; i < NV; i += blockDim.x) {
        float x = verts[3 * i + 0], y = verts[3 * i + 1], z = verts[3 * i + 2];
        float cx = sR[0] * x + sR[1] * y + sR[2] * z + sT[0];
        float cy = sR[3] * x + sR[4] * y + sR[5] * z + sT[1];
        float cz = sR[6] * x + sR[7] * y + sR[8] * z + sT[2];
        float u = sK[0] * cx + sK[1] * cy + sK[2] * cz;
        float v = sK[3] * cx + sK[4] * cy + sK[5] * cz;
        float w = sK[6] * cx + sK[7] * cy + sK[8] * cz;
        g_xy[i] = make_float2((u / w) * 0.4f, (v / w) * 0.4f);
    }
}

// ---------------------------------------------------------------------------
// Kernel 2: per-face edge coefficients  d_k = P_k*px + Q_k*py + C_k
// ---------------------------------------------------------------------------
__global__ void face_kernel(const int* __restrict__ faces) {
    int f = blockIdx.x * blockDim.x + threadIdx.x;
    if (f >= NF) return;
    int i0 = faces[3 * f + 0];
    int i1 = faces[3 * f + 1];
    int i2 = faces[3 * f + 2];
    float2 p0 = g_xy[i0], p1 = g_xy[i1], p2 = g_xy[i2];
    float2 e[3];
    e[0] = make_float2(p1.x - p0.x, p1.y - p0.y);
    e[1] = make_float2(p2.x - p1.x, p2.y - p1.y);
    e[2] = make_float2(p0.x - p2.x, p0.y - p2.y);
    float2 a[3] = {p0, p1, p2};
    float area2 = e[0].y * e[2].x - e[0].x * e[2].y;
    float sgn = (area2 >= 0.f) ? 1.f : -1.f;
    #pragma unroll
    for (int k = 0; k < 3; k++) {
        float elen = sqrtf(e[k].x * e[k].x + e[k].y * e[k].y) + 1e-9f;
        float s = sgn / elen;
        float c0 = e[k].x * a[k].y - e[k].y * a[k].x;
        g_face[f * 3 + k] = make_float4(-s * e[k].y, s * e[k].x, -s * c0, 0.f);
    }
}

// ---------------------------------------------------------------------------
// Kernel 3: rasterizer, 8x8 pixel tiles, 1024 CTAs x 256 threads.
//   Phase 1: ordered compaction of faces relevant to this tile.
//   Phase 2: 8 warps = 2 pixel-groups (8x4 px) x 4 contiguous face slices.
//            Per-slice partial product, early break when all lanes hit the
//            absorbing zero, lane-refined MUFU predicate.
//   Phase 3: combine 4 slice partials per pixel in ascending slice order.
// ---------------------------------------------------------------------------
__global__ __launch_bounds__(256) void raster_kernel() {
    __shared__ unsigned short slist[NF];
    __shared__ float sprod[4][2][32];
    __shared__ int swarp[8];
    __shared__ int scount;

    int tid  = threadIdx.x;
    int warp = tid >> 5, lane = tid & 31;
    int bx = blockIdx.x & 31, by = blockIdx.x >> 5;

    // tile pixel-center range: [8bx+0.5, 8bx+7.5] -> center 8bx+4, half 3.5
    float tcx = (float)(bx * 8 + 4);
    float tcy = (float)(by * 8 + 4);

    if (tid == 0) scount = 0;
    __syncthreads();

    // ---- Phase 1: ordered compaction of relevant faces ----
    for (int r = 0; r < NF / 256; r++) {
        int f = r * 256 + tid;
        float4 E0 = g_face[f * 3 + 0];
        float4 E1 = g_face[f * 3 + 1];
        float4 E2 = g_face[f * 3 + 2];
        float m0 = fmaf(E0.x, tcx, fmaf(E0.y, tcy, E0.z)) + 3.5f * (fabsf(E0.x) + fabsf(E0.y));
        float m1 = fmaf(E1.x, tcx, fmaf(E1.y, tcy, E1.z)) + 3.5f * (fabsf(E1.x) + fabsf(E1.y));
        float m2 = fmaf(E2.x, tcx, fmaf(E2.y, tcy, E2.z)) + 3.5f * (fabsf(E2.x) + fabsf(E2.y));
        bool keep = (m0 >= THRESH) && (m1 >= THRESH) && (m2 >= THRESH);

        unsigned b = __ballot_sync(0xffffffffu, keep);
        if (lane == 0) swarp[warp] = __popc(b);
        __syncthreads();
        int base = scount;
        #pragma unroll
        for (int w = 0; w < 8; w++) base += (w < warp) ? swarp[w] : 0;
        if (keep)
            slist[base + __popc(b & ((1u << lane) - 1u))] = (unsigned short)f;
        __syncthreads();
        if (tid == 0) {
            int tot = 0;
            #pragma unroll
            for (int w = 0; w < 8; w++) tot += swarp[w];
            scount += tot;
        }
        __syncthreads();
    }
    int nlist = scount;

    // ---- Phase 2: per-slice rasterization ----
    int pg    = warp & 1;     // pixel group: rows 0-3 vs 4-7
    int slice = warp >> 1;    // face slice 0..3
    int x = bx * 8 + (lane & 7);
    int y = by * 8 + pg * 4 + (lane >> 3);
    float px = (float)x + 0.5f;
    float py = (float)y + 0.5f;

    int s0 = (nlist * slice) >> 2;
    int s1 = (nlist * (slice + 1)) >> 2;

    float prod = 1.f;
    const float KEXP = 2.8853900817779268f;  // 2 * log2(e)

    #pragma unroll 2
    for (int i = s0; i < s1; i++) {
        int f = (int)slist[i];                 // warp-uniform
        float4 E0 = g_face[f * 3 + 0];
        float4 E1 = g_face[f * 3 + 1];
        float4 E2 = g_face[f * 3 + 2];
        float d0 = fmaf(E0.y, py, fmaf(E0.x, px, E0.z));
        float d1 = fmaf(E1.y, py, fmaf(E1.x, px, E1.z));
        float d2 = fmaf(E2.y, py, fmaf(E2.x, px, E2.z));
        float dmin = fminf(d0, fminf(d1, d2));
        bool active = (dmin > THRESH) && (prod != 0.f);
        if (__any_sync(0xffffffffu, active)) {
            if (active) {
                float t, rc;
                asm("ex2.approx.ftz.f32 %0, %1;" : "=f"(t) : "f"(dmin * KEXP));
                float den = 1.f + t;
                asm("rcp.approx.ftz.f32 %0, %1;" : "=f"(rc) : "f"(den));
                prod *= fmaxf(rc, 1e-6f);
            }
        }
        if (__all_sync(0xffffffffu, prod == 0.f)) break;   // absorbing zero
    }
    sprod[slice][pg][lane] = prod;
    __syncthreads();

    // ---- Phase 3: combine slice partials in ascending slice order ----
    if (tid < 64) {
        int cpg = tid >> 5;
        int cl  = tid & 31;
        float p = ((sprod[0][cpg][cl] * sprod[1][cpg][cl])
                  * sprod[2][cpg][cl]) * sprod[3][cpg][cl];
        int cx = bx * 8 + (cl & 7);
        int cy = by * 8 + cpg * 4 + (cl >> 3);
        g_si[cy * RS + cx] = 1.f - p;
    }
}

// ---------------------------------------------------------------------------
// Kernel 4: nearest upsample 256->640, crop, write si, partial SSE
// ---------------------------------------------------------------------------
__global__ __launch_bounds__(256) void finalize_kernel(const float* __restrict__ mask,
                                                       float* __restrict__ out,
                                                       int si_offset) {
    int idx = blockIdx.x * 256 + threadIdx.x;
    int r = idx / IMGW;
    int c = idx - r * IMGW;
    int sr = (2 * r + 1) / 5;
    int sc = (2 * c + 1) / 5;
    float si = g_si[sr * RS + sc];
    out[idx + si_offset] = si;
    float d = si - mask[idx];
    float sq = d * d;

    __shared__ float red[8];
    #pragma unroll
    for (int o = 16; o > 0; o >>= 1)
        sq += __shfl_down_sync(0xffffffffu, sq, o);
    int warp = threadIdx.x >> 5, lane = threadIdx.x & 31;
    if (lane == 0) red[warp] = sq;
    __syncthreads();
    if (threadIdx.x == 0) {
        float s = 0.f;
        #pragma unroll
        for (int w = 0; w < 8; w++) s += red[w];
        g_partial[blockIdx.x] = s;
    }
}

__global__ __launch_bounds__(256) void loss_kernel(float* __restrict__ out) {
    int tid = threadIdx.x;
    float s = 0.f;
    for (int i = tid; i < NBLK; i += 256) s += g_partial[i];
    __shared__ float red[256];
    red[tid] = s;
    __syncthreads();
    #pragma unroll
    for (int o = 128; o > 0; o >>= 1) {
        if (tid < o) red[tid] += red[tid + o];
        __syncthreads();
    }
    if (tid == 0) out[0] = red[0];
}

// ---------------------------------------------------------------------------
extern "C" void kernel_launch(void* const* d_in, const int* in_sizes, int n_in,
                              void* d_out, int out_size) {
    const float* dof   = (const float*)d_in[0];
    const float* verts = (const float*)d_in[1];
    const int*   faces = (const int*)d_in[2];
    const float* K     = (const float*)d_in[3];
    const float* mask  = (const float*)d_in[4];
    float* out = (float*)d_out;

    int has_loss = (out_size >= NPIX + 1) ? 1 : 0;

    setup_kernel<<<1, 256>>>(dof, verts, K);
    face_kernel<<<NF / 256, 256>>>(faces);
    raster_kernel<<<1024, 256>>>();
    finalize_kernel<<<NBLK, 256>>>(mask, out, has_loss);
    if (has_loss) loss_kernel<<<1, 256>>>(out);
}

// round 4
// speedup vs baseline: 1.8144x; 1.1095x over previous
#include <cuda_runtime.h>
#include <cstdint>

#define RS 256
#define NV 2048
#define NF 4096
#define IMGH 480
#define IMGW 640
#define NPIX (IMGH * IMGW)
#define NBLK (NPIX / 256)
#define THRESH (-10.0f)
#define NSUPER 64          // 8x8 super-tiles of 32x32 px

__device__ float2 g_xy[NV];
__device__ float4 g_face[NF * 3];
__device__ float  g_si[RS * RS];
__device__ float  g_partial[NBLK];
__device__ unsigned short g_superlist[NSUPER][NF];
__device__ int    g_supercount[NSUPER];

// ---------------------------------------------------------------------------
// Kernel 1: se3_exp + vertex transform + projection (tiny)
// ---------------------------------------------------------------------------
__global__ void setup_kernel(const float* __restrict__ dof,
                             const float* __restrict__ verts,
                             const float* __restrict__ Kin) {
    __shared__ float sR[9], sT[3], sK[9];
    int tid = threadIdx.x;
    if (tid == 0) {
        float v0 = dof[0], v1 = dof[1], v2 = dof[2];
        float w0 = dof[3], w1 = dof[4], w2 = dof[5];
        float th2 = w0 * w0 + w1 * w1 + w2 * w2;
        float th  = sqrtf(th2 + 1e-30f);
        bool small = th < 1e-4f;
        float th_s  = small ? 1.f : th;
        float th2_s = small ? 1.f : th2;
        float A = small ? (1.f - th2 / 6.f)   : (sinf(th_s) / th_s);
        float B = small ? (0.5f - th2 / 24.f) : ((1.f - cosf(th_s)) / th2_s);
        float C = small ? (1.f / 6.f - th2 / 120.f)
                        : ((th_s - sinf(th_s)) / (th2_s * th_s));
        float Kx[9] = {0.f, -w2,  w1,
                       w2,  0.f, -w0,
                      -w1,  w0,  0.f};
        float K2[9];
        #pragma unroll
        for (int r = 0; r < 3; r++)
            #pragma unroll
            for (int c = 0; c < 3; c++) {
                float acc = 0.f;
                #pragma unroll
                for (int k = 0; k < 3; k++) acc += Kx[r * 3 + k] * Kx[k * 3 + c];
                K2[r * 3 + c] = acc;
            }
        float V[9];
        #pragma unroll
        for (int i = 0; i < 9; i++) {
            float I = (i == 0 || i == 4 || i == 8) ? 1.f : 0.f;
            sR[i] = I + A * Kx[i] + B * K2[i];
            V[i]  = I + B * Kx[i] + C * K2[i];
        }
        sT[0] = V[0] * v0 + V[1] * v1 + V[2] * v2;
        sT[1] = V[3] * v0 + V[4] * v1 + V[5] * v2;
        sT[2] = V[6] * v0 + V[7] * v1 + V[8] * v2;
    }
    if (tid < 9) sK[tid] = Kin[tid];
    __syncthreads();
    for (int i = tid; i < NV; i += blockDim.x) {
        float x = verts[3 * i + 0], y = verts[3 * i + 1], z = verts[3 * i + 2];
        float cx = sR[0] * x + sR[1] * y + sR[2] * z + sT[0];
        float cy = sR[3] * x + sR[4] * y + sR[5] * z + sT[1];
        float cz = sR[6] * x + sR[7] * y + sR[8] * z + sT[2];
        float u = sK[0] * cx + sK[1] * cy + sK[2] * cz;
        float v = sK[3] * cx + sK[4] * cy + sK[5] * cz;
        float w = sK[6] * cx + sK[7] * cy + sK[8] * cz;
        g_xy[i] = make_float2((u / w) * 0.4f, (v / w) * 0.4f);
    }
}

// ---------------------------------------------------------------------------
// Kernel 2: per-face edge coefficients  d_k = P_k*px + Q_k*py + C_k
// ---------------------------------------------------------------------------
__global__ void face_kernel(const int* __restrict__ faces) {
    int f = blockIdx.x * blockDim.x + threadIdx.x;
    if (f >= NF) return;
    int i0 = faces[3 * f + 0];
    int i1 = faces[3 * f + 1];
    int i2 = faces[3 * f + 2];
    float2 p0 = g_xy[i0], p1 = g_xy[i1], p2 = g_xy[i2];
    float2 e[3];
    e[0] = make_float2(p1.x - p0.x, p1.y - p0.y);
    e[1] = make_float2(p2.x - p1.x, p2.y - p1.y);
    e[2] = make_float2(p0.x - p2.x, p0.y - p2.y);
    float2 a[3] = {p0, p1, p2};
    float area2 = e[0].y * e[2].x - e[0].x * e[2].y;
    float sgn = (area2 >= 0.f) ? 1.f : -1.f;
    #pragma unroll
    for (int k = 0; k < 3; k++) {
        float elen = sqrtf(e[k].x * e[k].x + e[k].y * e[k].y) + 1e-9f;
        float s = sgn / elen;
        float c0 = e[k].x * a[k].y - e[k].y * a[k].x;
        g_face[f * 3 + k] = make_float4(-s * e[k].y, s * e[k].x, -s * c0, 0.f);
    }
}

// ---------------------------------------------------------------------------
// Kernel 2b: super-tile cull. One CTA per 32x32-px super-tile; ordered
// compaction of all faces into a global per-super-tile list.
// max over tile of (P*px+Q*py+C) = d(center) + half*(|P|+|Q|)  (exact).
// ---------------------------------------------------------------------------
__global__ __launch_bounds__(256) void supercull_kernel() {
    __shared__ int swarp[8];
    __shared__ int scount;
    int tid  = threadIdx.x;
    int warp = tid >> 5, lane = tid & 31;
    int sx = blockIdx.x & 7, sy = blockIdx.x >> 3;
    float tcx = (float)(sx * 32 + 16);
    float tcy = (float)(sy * 32 + 16);

    if (tid == 0) scount = 0;
    __syncthreads();

    for (int r = 0; r < NF / 256; r++) {
        int f = r * 256 + tid;
        float4 E0 = g_face[f * 3 + 0];
        float4 E1 = g_face[f * 3 + 1];
        float4 E2 = g_face[f * 3 + 2];
        float m0 = fmaf(E0.x, tcx, fmaf(E0.y, tcy, E0.z)) + 15.5f * (fabsf(E0.x) + fabsf(E0.y));
        float m1 = fmaf(E1.x, tcx, fmaf(E1.y, tcy, E1.z)) + 15.5f * (fabsf(E1.x) + fabsf(E1.y));
        float m2 = fmaf(E2.x, tcx, fmaf(E2.y, tcy, E2.z)) + 15.5f * (fabsf(E2.x) + fabsf(E2.y));
        bool keep = (m0 >= THRESH) && (m1 >= THRESH) && (m2 >= THRESH);

        unsigned b = __ballot_sync(0xffffffffu, keep);
        if (lane == 0) swarp[warp] = __popc(b);
        __syncthreads();
        int base = scount;
        #pragma unroll
        for (int w = 0; w < 8; w++) base += (w < warp) ? swarp[w] : 0;
        if (keep)
            g_superlist[blockIdx.x][base + __popc(b & ((1u << lane) - 1u))] = (unsigned short)f;
        __syncthreads();
        if (tid == 0) {
            int tot = 0;
            #pragma unroll
            for (int w = 0; w < 8; w++) tot += swarp[w];
            scount += tot;
        }
        __syncthreads();
    }
    if (tid == 0) g_supercount[blockIdx.x] = scount;
}

// ---------------------------------------------------------------------------
// Kernel 3: rasterizer, 8x8 pixel tiles, 1024 CTAs x 256 threads.
//   Phase 1: fine cull from this tile's SUPER-tile list (ordered compaction).
//   Phase 2: 8 warps = 2 pixel-groups (8x4 px) x 4 contiguous face slices.
//   Phase 3: combine slice partials in ascending slice order.
// ---------------------------------------------------------------------------
__global__ __launch_bounds__(256) void raster_kernel() {
    __shared__ unsigned short slist[NF];
    __shared__ float sprod[4][2][32];
    __shared__ int swarp[8];
    __shared__ int scount;

    int tid  = threadIdx.x;
    int warp = tid >> 5, lane = tid & 31;
    int bx = blockIdx.x & 31, by = blockIdx.x >> 5;
    int stile = (by >> 2) * 8 + (bx >> 2);
    int supn = g_supercount[stile];

    int pg    = warp & 1;     // pixel group: rows 0-3 vs 4-7
    int slice = warp >> 1;    // face slice 0..3
    int x = bx * 8 + (lane & 7);
    int y = by * 8 + pg * 4 + (lane >> 3);

    if (supn == 0) {                       // empty sky tile
        if (tid < 64) {
            int cpg = tid >> 5, cl = tid & 31;
            g_si[(by * 8 + cpg * 4 + (cl >> 3)) * RS + bx * 8 + (cl & 7)] = 0.f;
        }
        return;
    }

    float tcx = (float)(bx * 8 + 4);
    float tcy = (float)(by * 8 + 4);

    if (tid == 0) scount = 0;
    __syncthreads();

    // ---- Phase 1: fine cull from super-list ----
    const unsigned short* sup = g_superlist[stile];
    for (int r = 0; r < supn; r += 256) {
        int j = r + tid;
        bool keep = false;
        int f = 0;
        if (j < supn) {
            f = (int)sup[j];
            float4 E0 = g_face[f * 3 + 0];
            float4 E1 = g_face[f * 3 + 1];
            float4 E2 = g_face[f * 3 + 2];
            float m0 = fmaf(E0.x, tcx, fmaf(E0.y, tcy, E0.z)) + 3.5f * (fabsf(E0.x) + fabsf(E0.y));
            float m1 = fmaf(E1.x, tcx, fmaf(E1.y, tcy, E1.z)) + 3.5f * (fabsf(E1.x) + fabsf(E1.y));
            float m2 = fmaf(E2.x, tcx, fmaf(E2.y, tcy, E2.z)) + 3.5f * (fabsf(E2.x) + fabsf(E2.y));
            keep = (m0 >= THRESH) && (m1 >= THRESH) && (m2 >= THRESH);
        }
        unsigned b = __ballot_sync(0xffffffffu, keep);
        if (lane == 0) swarp[warp] = __popc(b);
        __syncthreads();
        int base = scount;
        #pragma unroll
        for (int w = 0; w < 8; w++) base += (w < warp) ? swarp[w] : 0;
        if (keep)
            slist[base + __popc(b & ((1u << lane) - 1u))] = (unsigned short)f;
        __syncthreads();
        if (tid == 0) {
            int tot = 0;
            #pragma unroll
            for (int w = 0; w < 8; w++) tot += swarp[w];
            scount += tot;
        }
        __syncthreads();
    }
    int nlist = scount;

    // ---- Phase 2: per-slice rasterization ----
    float px = (float)x + 0.5f;
    float py = (float)y + 0.5f;

    int s0 = (nlist * slice) >> 2;
    int s1 = (nlist * (slice + 1)) >> 2;

    float prod = 1.f;
    const float KEXP = 2.8853900817779268f;  // 2 * log2(e)

    #pragma unroll 2
    for (int i = s0; i < s1; i++) {
        int f = (int)slist[i];                 // warp-uniform
        float4 E0 = g_face[f * 3 + 0];
        float4 E1 = g_face[f * 3 + 1];
        float4 E2 = g_face[f * 3 + 2];
        float d0 = fmaf(E0.y, py, fmaf(E0.x, px, E0.z));
        float d1 = fmaf(E1.y, py, fmaf(E1.x, px, E1.z));
        float d2 = fmaf(E2.y, py, fmaf(E2.x, px, E2.z));
        float dmin = fminf(d0, fminf(d1, d2));
        bool active = (dmin > THRESH) && (prod != 0.f);
        if (__any_sync(0xffffffffu, active)) {
            if (active) {
                float t, rc;
                asm("ex2.approx.ftz.f32 %0, %1;" : "=f"(t) : "f"(dmin * KEXP));
                float den = 1.f + t;
                asm("rcp.approx.ftz.f32 %0, %1;" : "=f"(rc) : "f"(den));
                prod *= fmaxf(rc, 1e-6f);
            }
        }
        // absorbing-zero break, checked every 8 iterations
        if (((i & 7) == 7) && __all_sync(0xffffffffu, prod == 0.f)) break;
    }
    sprod[slice][pg][lane] = prod;
    __syncthreads();

    // ---- Phase 3: combine slice partials in ascending slice order ----
    if (tid < 64) {
        int cpg = tid >> 5;
        int cl  = tid & 31;
        float p = ((sprod[0][cpg][cl] * sprod[1][cpg][cl])
                  * sprod[2][cpg][cl]) * sprod[3][cpg][cl];
        int cx = bx * 8 + (cl & 7);
        int cy = by * 8 + cpg * 4 + (cl >> 3);
        g_si[cy * RS + cx] = 1.f - p;
    }
}

// ---------------------------------------------------------------------------
// Kernel 4: nearest upsample 256->640, crop, write si, partial SSE
// ---------------------------------------------------------------------------
__global__ __launch_bounds__(256) void finalize_kernel(const float* __restrict__ mask,
                                                       float* __restrict__ out,
                                                       int si_offset) {
    int idx = blockIdx.x * 256 + threadIdx.x;
    int r = idx / IMGW;
    int c = idx - r * IMGW;
    int sr = (2 * r + 1) / 5;
    int sc = (2 * c + 1) / 5;
    float si = g_si[sr * RS + sc];
    out[idx + si_offset] = si;
    float d = si - mask[idx];
    float sq = d * d;

    __shared__ float red[8];
    #pragma unroll
    for (int o = 16; o > 0; o >>= 1)
        sq += __shfl_down_sync(0xffffffffu, sq, o);
    int warp = threadIdx.x >> 5, lane = threadIdx.x & 31;
    if (lane == 0) red[warp] = sq;
    __syncthreads();
    if (threadIdx.x == 0) {
        float s = 0.f;
        #pragma unroll
        for (int w = 0; w < 8; w++) s += red[w];
        g_partial[blockIdx.x] = s;
    }
}

__global__ __launch_bounds__(256) void loss_kernel(float* __restrict__ out) {
    int tid = threadIdx.x;
    float s = 0.f;
    for (int i = tid; i < NBLK; i += 256) s += g_partial[i];
    __shared__ float red[256];
    red[tid] = s;
    __syncthreads();
    #pragma unroll
    for (int o = 128; o > 0; o >>= 1) {
        if (tid < o) red[tid] += red[tid + o];
        __syncthreads();
    }
    if (tid == 0) out[0] = red[0];
}

// ---------------------------------------------------------------------------
extern "C" void kernel_launch(void* const* d_in, const int* in_sizes, int n_in,
                              void* d_out, int out_size) {
    const float* dof   = (const float*)d_in[0];
    const float* verts = (const float*)d_in[1];
    const int*   faces = (const int*)d_in[2];
    const float* K     = (const float*)d_in[3];
    const float* mask  = (const float*)d_in[4];
    float* out = (float*)d_out;

    int has_loss = (out_size >= NPIX + 1) ? 1 : 0;

    setup_kernel<<<1, 256>>>(dof, verts, K);
    face_kernel<<<NF / 256, 256>>>(faces);
    supercull_kernel<<<NSUPER, 256>>>();
    raster_kernel<<<1024, 256>>>();
    finalize_kernel<<<NBLK, 256>>>(mask, out, has_loss);
    if (has_loss) loss_kernel<<<1, 256>>>(out);
}

// round 5
// speedup vs baseline: 2.7294x; 1.5043x over previous
#include <cuda_runtime.h>
#include <cstdint>

#define RS 256
#define NV 2048
#define NF 4096
#define IMGH 480
#define IMGW 640
#define NPIX (IMGH * IMGW)
#define NBLK (NPIX / 256)
#define THRESH (-10.0f)
#define NSUPER 64          // 8x8 super-tiles of 32x32 px
#define RT 512             // raster CTA threads

__device__ float2 g_xy[NV];
__device__ float4 g_face[NF * 3];
__device__ float  g_si[RS * RS];
__device__ float  g_partial[NBLK];
__device__ unsigned short g_superlist[NSUPER][NF];
__device__ int    g_supercount[NSUPER];

// ---------------------------------------------------------------------------
// Kernel 1: se3_exp + vertex transform + projection (tiny)
// ---------------------------------------------------------------------------
__global__ void setup_kernel(const float* __restrict__ dof,
                             const float* __restrict__ verts,
                             const float* __restrict__ Kin) {
    __shared__ float sR[9], sT[3], sK[9];
    int tid = threadIdx.x;
    if (tid == 0) {
        float v0 = dof[0], v1 = dof[1], v2 = dof[2];
        float w0 = dof[3], w1 = dof[4], w2 = dof[5];
        float th2 = w0 * w0 + w1 * w1 + w2 * w2;
        float th  = sqrtf(th2 + 1e-30f);
        bool small = th < 1e-4f;
        float th_s  = small ? 1.f : th;
        float th2_s = small ? 1.f : th2;
        float A = small ? (1.f - th2 / 6.f)   : (sinf(th_s) / th_s);
        float B = small ? (0.5f - th2 / 24.f) : ((1.f - cosf(th_s)) / th2_s);
        float C = small ? (1.f / 6.f - th2 / 120.f)
                        : ((th_s - sinf(th_s)) / (th2_s * th_s));
        float Kx[9] = {0.f, -w2,  w1,
                       w2,  0.f, -w0,
                      -w1,  w0,  0.f};
        float K2[9];
        #pragma unroll
        for (int r = 0; r < 3; r++)
            #pragma unroll
            for (int c = 0; c < 3; c++) {
                float acc = 0.f;
                #pragma unroll
                for (int k = 0; k < 3; k++) acc += Kx[r * 3 + k] * Kx[k * 3 + c];
                K2[r * 3 + c] = acc;
            }
        float V[9];
        #pragma unroll
        for (int i = 0; i < 9; i++) {
            float I = (i == 0 || i == 4 || i == 8) ? 1.f : 0.f;
            sR[i] = I + A * Kx[i] + B * K2[i];
            V[i]  = I + B * Kx[i] + C * K2[i];
        }
        sT[0] = V[0] * v0 + V[1] * v1 + V[2] * v2;
        sT[1] = V[3] * v0 + V[4] * v1 + V[5] * v2;
        sT[2] = V[6] * v0 + V[7] * v1 + V[8] * v2;
    }
    if (tid < 9) sK[tid] = Kin[tid];
    __syncthreads();
    for (int i = tid; i < NV; i += blockDim.x) {
        float x = verts[3 * i + 0], y = verts[3 * i + 1], z = verts[3 * i + 2];
        float cx = sR[0] * x + sR[1] * y + sR[2] * z + sT[0];
        float cy = sR[3] * x + sR[4] * y + sR[5] * z + sT[1];
        float cz = sR[6] * x + sR[7] * y + sR[8] * z + sT[2];
        float u = sK[0] * cx + sK[1] * cy + sK[2] * cz;
        float v = sK[3] * cx + sK[4] * cy + sK[5] * cz;
        float w = sK[6] * cx + sK[7] * cy + sK[8] * cz;
        g_xy[i] = make_float2((u / w) * 0.4f, (v / w) * 0.4f);
    }
}

// ---------------------------------------------------------------------------
// Kernel 2: per-face edge coefficients  d_k = P_k*px + Q_k*py + C_k
// ---------------------------------------------------------------------------
__global__ void face_kernel(const int* __restrict__ faces) {
    int f = blockIdx.x * blockDim.x + threadIdx.x;
    if (f >= NF) return;
    int i0 = faces[3 * f + 0];
    int i1 = faces[3 * f + 1];
    int i2 = faces[3 * f + 2];
    float2 p0 = g_xy[i0], p1 = g_xy[i1], p2 = g_xy[i2];
    float2 e[3];
    e[0] = make_float2(p1.x - p0.x, p1.y - p0.y);
    e[1] = make_float2(p2.x - p1.x, p2.y - p1.y);
    e[2] = make_float2(p0.x - p2.x, p0.y - p2.y);
    float2 a[3] = {p0, p1, p2};
    float area2 = e[0].y * e[2].x - e[0].x * e[2].y;
    float sgn = (area2 >= 0.f) ? 1.f : -1.f;
    #pragma unroll
    for (int k = 0; k < 3; k++) {
        float elen = sqrtf(e[k].x * e[k].x + e[k].y * e[k].y) + 1e-9f;
        float s = sgn / elen;
        float c0 = e[k].x * a[k].y - e[k].y * a[k].x;
        g_face[f * 3 + k] = make_float4(-s * e[k].y, s * e[k].x, -s * c0, 0.f);
    }
}

// ---------------------------------------------------------------------------
// Kernel 2b: super-tile cull (32x32 px), ordered compaction into global list.
// ---------------------------------------------------------------------------
__global__ __launch_bounds__(256) void supercull_kernel() {
    __shared__ int swarp[8];
    __shared__ int scount;
    int tid  = threadIdx.x;
    int warp = tid >> 5, lane = tid & 31;
    int sx = blockIdx.x & 7, sy = blockIdx.x >> 3;
    float tcx = (float)(sx * 32 + 16);
    float tcy = (float)(sy * 32 + 16);

    if (tid == 0) scount = 0;
    __syncthreads();

    for (int r = 0; r < NF / 256; r++) {
        int f = r * 256 + tid;
        float4 E0 = g_face[f * 3 + 0];
        float4 E1 = g_face[f * 3 + 1];
        float4 E2 = g_face[f * 3 + 2];
        float m0 = fmaf(E0.x, tcx, fmaf(E0.y, tcy, E0.z)) + 15.5f * (fabsf(E0.x) + fabsf(E0.y));
        float m1 = fmaf(E1.x, tcx, fmaf(E1.y, tcy, E1.z)) + 15.5f * (fabsf(E1.x) + fabsf(E1.y));
        float m2 = fmaf(E2.x, tcx, fmaf(E2.y, tcy, E2.z)) + 15.5f * (fabsf(E2.x) + fabsf(E2.y));
        bool keep = (m0 >= THRESH) && (m1 >= THRESH) && (m2 >= THRESH);

        unsigned b = __ballot_sync(0xffffffffu, keep);
        if (lane == 0) swarp[warp] = __popc(b);
        __syncthreads();
        int base = scount;
        #pragma unroll
        for (int w = 0; w < 8; w++) base += (w < warp) ? swarp[w] : 0;
        if (keep)
            g_superlist[blockIdx.x][base + __popc(b & ((1u << lane) - 1u))] = (unsigned short)f;
        __syncthreads();
        if (tid == 0) {
            int tot = 0;
            #pragma unroll
            for (int w = 0; w < 8; w++) tot += swarp[w];
            scount += tot;
        }
        __syncthreads();
    }
    if (tid == 0) g_supercount[blockIdx.x] = scount;
}

// ---------------------------------------------------------------------------
// Kernel 3: rasterizer, 8x8 px tiles, 1024 CTAs x 512 threads.
//   Phase 1: fine cull from super-tile list (ordered compaction).
//   Phase 2: 16 warps = 2 pixel-groups (8x4 px) x 8 contiguous face slices.
//            Software-pipelined face fetch; absorbing-zero break.
//   Phase 3: combine 8 slice partials per pixel in ascending slice order.
// ---------------------------------------------------------------------------
__global__ __launch_bounds__(RT) void raster_kernel() {
    __shared__ unsigned short slist[NF];
    __shared__ float sprod[8][2][32];
    __shared__ int swarp[16];
    __shared__ int scount;

    int tid  = threadIdx.x;
    int warp = tid >> 5, lane = tid & 31;
    int bx = blockIdx.x & 31, by = blockIdx.x >> 5;
    int stile = (by >> 2) * 8 + (bx >> 2);
    int supn = g_supercount[stile];

    if (supn == 0) {                       // empty sky tile
        if (tid < 64) {
            int cpg = tid >> 5, cl = tid & 31;
            g_si[(by * 8 + cpg * 4 + (cl >> 3)) * RS + bx * 8 + (cl & 7)] = 0.f;
        }
        return;
    }

    float tcx = (float)(bx * 8 + 4);
    float tcy = (float)(by * 8 + 4);

    if (tid == 0) scount = 0;
    __syncthreads();

    // ---- Phase 1: fine cull from super-list (512 threads/round) ----
    const unsigned short* sup = g_superlist[stile];
    for (int r = 0; r < supn; r += RT) {
        int j = r + tid;
        bool keep = false;
        int f = 0;
        if (j < supn) {
            f = (int)sup[j];
            float4 E0 = g_face[f * 3 + 0];
            float4 E1 = g_face[f * 3 + 1];
            float4 E2 = g_face[f * 3 + 2];
            float m0 = fmaf(E0.x, tcx, fmaf(E0.y, tcy, E0.z)) + 3.5f * (fabsf(E0.x) + fabsf(E0.y));
            float m1 = fmaf(E1.x, tcx, fmaf(E1.y, tcy, E1.z)) + 3.5f * (fabsf(E1.x) + fabsf(E1.y));
            float m2 = fmaf(E2.x, tcx, fmaf(E2.y, tcy, E2.z)) + 3.5f * (fabsf(E2.x) + fabsf(E2.y));
            keep = (m0 >= THRESH) && (m1 >= THRESH) && (m2 >= THRESH);
        }
        unsigned b = __ballot_sync(0xffffffffu, keep);
        if (lane == 0) swarp[warp] = __popc(b);
        __syncthreads();
        int base = scount;
        #pragma unroll
        for (int w = 0; w < 16; w++) base += (w < warp) ? swarp[w] : 0;
        if (keep)
            slist[base + __popc(b & ((1u << lane) - 1u))] = (unsigned short)f;
        __syncthreads();
        if (tid == 0) {
            int tot = 0;
            #pragma unroll
            for (int w = 0; w < 16; w++) tot += swarp[w];
            scount += tot;
        }
        __syncthreads();
    }
    int nlist = scount;

    // ---- Phase 2: per-slice rasterization, software-pipelined ----
    int pg    = warp & 1;     // pixel group: rows 0-3 vs 4-7
    int slice = warp >> 1;    // face slice 0..7
    int x = bx * 8 + (lane & 7);
    int y = by * 8 + pg * 4 + (lane >> 3);
    float px = (float)x + 0.5f;
    float py = (float)y + 0.5f;

    int s0 = (nlist * slice) >> 3;
    int s1 = (nlist * (slice + 1)) >> 3;

    float prod = 1.f;
    const float KEXP = 2.8853900817779268f;  // 2 * log2(e)

    float4 N0, N1, N2;
    if (s0 < s1) {
        int f = (int)slist[s0];
        N0 = g_face[f * 3 + 0];
        N1 = g_face[f * 3 + 1];
        N2 = g_face[f * 3 + 2];
    }
    for (int i = s0; i < s1; i++) {
        float4 E0 = N0, E1 = N1, E2 = N2;
        int inext = i + 1;
        if (inext < s1) {                      // prefetch next face
            int f = (int)slist[inext];
            N0 = g_face[f * 3 + 0];
            N1 = g_face[f * 3 + 1];
            N2 = g_face[f * 3 + 2];
        }
        float d0 = fmaf(E0.y, py, fmaf(E0.x, px, E0.z));
        float d1 = fmaf(E1.y, py, fmaf(E1.x, px, E1.z));
        float d2 = fmaf(E2.y, py, fmaf(E2.x, px, E2.z));
        float dmin = fminf(d0, fminf(d1, d2));
        bool active = (dmin > THRESH) && (prod != 0.f);
        if (__any_sync(0xffffffffu, active)) {
            if (active) {
                float t, rc;
                asm("ex2.approx.ftz.f32 %0, %1;" : "=f"(t) : "f"(dmin * KEXP));
                float den = 1.f + t;
                asm("rcp.approx.ftz.f32 %0, %1;" : "=f"(rc) : "f"(den));
                prod *= fmaxf(rc, 1e-6f);
            }
        }
        // absorbing-zero break, checked every 8 iterations
        if (((i & 7) == 7) && __all_sync(0xffffffffu, prod == 0.f)) break;
    }
    sprod[slice][pg][lane] = prod;
    __syncthreads();

    // ---- Phase 3: combine slice partials in ascending slice order ----
    if (tid < 64) {
        int cpg = tid >> 5;
        int cl  = tid & 31;
        float p = sprod[0][cpg][cl];
        #pragma unroll
        for (int s = 1; s < 8; s++) p *= sprod[s][cpg][cl];
        int cx = bx * 8 + (cl & 7);
        int cy = by * 8 + cpg * 4 + (cl >> 3);
        g_si[cy * RS + cx] = 1.f - p;
    }
}

// ---------------------------------------------------------------------------
// Kernel 4: nearest upsample 256->640, crop, write si, partial SSE
// ---------------------------------------------------------------------------
__global__ __launch_bounds__(256) void finalize_kernel(const float* __restrict__ mask,
                                                       float* __restrict__ out,
                                                       int si_offset) {
    int idx = blockIdx.x * 256 + threadIdx.x;
    int r = idx / IMGW;
    int c = idx - r * IMGW;
    int sr = (2 * r + 1) / 5;
    int sc = (2 * c + 1) / 5;
    float si = g_si[sr * RS + sc];
    out[idx + si_offset] = si;
    float d = si - mask[idx];
    float sq = d * d;

    __shared__ float red[8];
    #pragma unroll
    for (int o = 16; o > 0; o >>= 1)
        sq += __shfl_down_sync(0xffffffffu, sq, o);
    int warp = threadIdx.x >> 5, lane = threadIdx.x & 31;
    if (lane == 0) red[warp] = sq;
    __syncthreads();
    if (threadIdx.x == 0) {
        float s = 0.f;
        #pragma unroll
        for (int w = 0; w < 8; w++) s += red[w];
        g_partial[blockIdx.x] = s;
    }
}

__global__ __launch_bounds__(256) void loss_kernel(float* __restrict__ out) {
    int tid = threadIdx.x;
    float s = 0.f;
    for (int i = tid; i < NBLK; i += 256) s += g_partial[i];
    __shared__ float red[256];
    red[tid] = s;
    __syncthreads();
    #pragma unroll
    for (int o = 128; o > 0; o >>= 1) {
        if (tid < o) red[tid] += red[tid + o];
        __syncthreads();
    }
    if (tid == 0) out[0] = red[0];
}

// ---------------------------------------------------------------------------
extern "C" void kernel_launch(void* const* d_in, const int* in_sizes, int n_in,
                              void* d_out, int out_size) {
    const float* dof   = (const float*)d_in[0];
    const float* verts = (const float*)d_in[1];
    const int*   faces = (const int*)d_in[2];
    const float* K     = (const float*)d_in[3];
    const float* mask  = (const float*)d_in[4];
    float* out = (float*)d_out;

    int has_loss = (out_size >= NPIX + 1) ? 1 : 0;

    setup_kernel<<<1, 256>>>(dof, verts, K);
    face_kernel<<<NF / 256, 256>>>(faces);
    supercull_kernel<<<NSUPER, 256>>>();
    raster_kernel<<<1024, RT>>>();
    finalize_kernel<<<NBLK, 256>>>(mask, out, has_loss);
    if (has_loss) loss_kernel<<<1, 256>>>(out);
}

// round 6
// speedup vs baseline: 3.1999x; 1.1724x over previous
#include <cuda_runtime.h>
#include <cstdint>

#define RS 256
#define NV 2048
#define NF 4096
#define IMGH 480
#define IMGW 640
#define NPIX (IMGH * IMGW)
#define NBLK (NPIX / 256)
#define THRESH (-10.0f)
#define NSUPER 64          // 8x8 super-tiles of 32x32 px
#define RT 512             // raster CTA threads
#define CHUNK 512          // faces per cull/raster round

__device__ float4 g_face[NF * 3];
__device__ float  g_si[RS * RS];
__device__ float  g_partial[NBLK];
__device__ unsigned short g_superlist[NSUPER][NF];
__device__ int    g_supercount[NSUPER];

// ---------------------------------------------------------------------------
// Kernel 1: fused se3_exp + vertex transform + projection + face coefficients
// ---------------------------------------------------------------------------
__global__ __launch_bounds__(512) void setup_face_kernel(
        const float* __restrict__ dof,
        const float* __restrict__ verts,
        const float* __restrict__ Kin,
        const int*   __restrict__ faces) {
    __shared__ float2 sxy[NV];
    __shared__ float sR[9], sT[3], sK[9];
    int tid = threadIdx.x;
    if (tid == 0) {
        float v0 = dof[0], v1 = dof[1], v2 = dof[2];
        float w0 = dof[3], w1 = dof[4], w2 = dof[5];
        float th2 = w0 * w0 + w1 * w1 + w2 * w2;
        float th  = sqrtf(th2 + 1e-30f);
        bool small = th < 1e-4f;
        float th_s  = small ? 1.f : th;
        float th2_s = small ? 1.f : th2;
        float A = small ? (1.f - th2 / 6.f)   : (sinf(th_s) / th_s);
        float B = small ? (0.5f - th2 / 24.f) : ((1.f - cosf(th_s)) / th2_s);
        float C = small ? (1.f / 6.f - th2 / 120.f)
                        : ((th_s - sinf(th_s)) / (th2_s * th_s));
        float Kx[9] = {0.f, -w2,  w1,
                       w2,  0.f, -w0,
                      -w1,  w0,  0.f};
        float K2[9];
        #pragma unroll
        for (int r = 0; r < 3; r++)
            #pragma unroll
            for (int c = 0; c < 3; c++) {
                float acc = 0.f;
                #pragma unroll
                for (int k = 0; k < 3; k++) acc += Kx[r * 3 + k] * Kx[k * 3 + c];
                K2[r * 3 + c] = acc;
            }
        float V[9];
        #pragma unroll
        for (int i = 0; i < 9; i++) {
            float I = (i == 0 || i == 4 || i == 8) ? 1.f : 0.f;
            sR[i] = I + A * Kx[i] + B * K2[i];
            V[i]  = I + B * Kx[i] + C * K2[i];
        }
        sT[0] = V[0] * v0 + V[1] * v1 + V[2] * v2;
        sT[1] = V[3] * v0 + V[4] * v1 + V[5] * v2;
        sT[2] = V[6] * v0 + V[7] * v1 + V[8] * v2;
    }
    if (tid < 9) sK[tid] = Kin[tid];
    __syncthreads();
    for (int i = tid; i < NV; i += 512) {
        float x = verts[3 * i + 0], y = verts[3 * i + 1], z = verts[3 * i + 2];
        float cx = sR[0] * x + sR[1] * y + sR[2] * z + sT[0];
        float cy = sR[3] * x + sR[4] * y + sR[5] * z + sT[1];
        float cz = sR[6] * x + sR[7] * y + sR[8] * z + sT[2];
        float u = sK[0] * cx + sK[1] * cy + sK[2] * cz;
        float v = sK[3] * cx + sK[4] * cy + sK[5] * cz;
        float w = sK[6] * cx + sK[7] * cy + sK[8] * cz;
        sxy[i] = make_float2((u / w) * 0.4f, (v / w) * 0.4f);
    }
    __syncthreads();
    for (int f = tid; f < NF; f += 512) {
        int i0 = faces[3 * f + 0];
        int i1 = faces[3 * f + 1];
        int i2 = faces[3 * f + 2];
        float2 p0 = sxy[i0], p1 = sxy[i1], p2 = sxy[i2];
        float2 e[3];
        e[0] = make_float2(p1.x - p0.x, p1.y - p0.y);
        e[1] = make_float2(p2.x - p1.x, p2.y - p1.y);
        e[2] = make_float2(p0.x - p2.x, p0.y - p2.y);
        float2 a[3] = {p0, p1, p2};
        float area2 = e[0].y * e[2].x - e[0].x * e[2].y;
        float sgn = (area2 >= 0.f) ? 1.f : -1.f;
        #pragma unroll
        for (int k = 0; k < 3; k++) {
            float elen = sqrtf(e[k].x * e[k].x + e[k].y * e[k].y) + 1e-9f;
            float s = sgn / elen;
            float c0 = e[k].x * a[k].y - e[k].y * a[k].x;
            g_face[f * 3 + k] = make_float4(-s * e[k].y, s * e[k].x, -s * c0, 0.f);
        }
    }
}

// ---------------------------------------------------------------------------
// Kernel 2: super-tile cull (32x32 px), ordered compaction into global list.
// ---------------------------------------------------------------------------
__global__ __launch_bounds__(256) void supercull_kernel() {
    __shared__ int swarp[8];
    __shared__ int scount;
    int tid  = threadIdx.x;
    int warp = tid >> 5, lane = tid & 31;
    int sx = blockIdx.x & 7, sy = blockIdx.x >> 3;
    float tcx = (float)(sx * 32 + 16);
    float tcy = (float)(sy * 32 + 16);

    if (tid == 0) scount = 0;
    __syncthreads();

    for (int r = 0; r < NF / 256; r++) {
        int f = r * 256 + tid;
        float4 E0 = g_face[f * 3 + 0];
        float4 E1 = g_face[f * 3 + 1];
        float4 E2 = g_face[f * 3 + 2];
        float m0 = fmaf(E0.x, tcx, fmaf(E0.y, tcy, E0.z)) + 15.5f * (fabsf(E0.x) + fabsf(E0.y));
        float m1 = fmaf(E1.x, tcx, fmaf(E1.y, tcy, E1.z)) + 15.5f * (fabsf(E1.x) + fabsf(E1.y));
        float m2 = fmaf(E2.x, tcx, fmaf(E2.y, tcy, E2.z)) + 15.5f * (fabsf(E2.x) + fabsf(E2.y));
        bool keep = (m0 >= THRESH) && (m1 >= THRESH) && (m2 >= THRESH);

        unsigned b = __ballot_sync(0xffffffffu, keep);
        if (lane == 0) swarp[warp] = __popc(b);
        __syncthreads();
        int base = scount;
        #pragma unroll
        for (int w = 0; w < 8; w++) base += (w < warp) ? swarp[w] : 0;
        if (keep)
            g_superlist[blockIdx.x][base + __popc(b & ((1u << lane) - 1u))] = (unsigned short)f;
        __syncthreads();
        if (tid == 0) {
            int tot = 0;
            #pragma unroll
            for (int w = 0; w < 8; w++) tot += swarp[w];
            scount += tot;
        }
        __syncthreads();
    }
    if (tid == 0) g_supercount[blockIdx.x] = scount;
}

// ---------------------------------------------------------------------------
// Kernel 3: rasterizer, 8x8 px tiles, 1024 CTAs x 512 threads.
// Chunked: per 512-face chunk of the super-list:
//   cull -> compacted face data staged in smem -> 16 warps (8 slices x 2 pg)
//   raster from smem -> CTA-wide absorbing-zero break.
// ---------------------------------------------------------------------------
__global__ __launch_bounds__(RT) void raster_kernel() {
    __shared__ float4 sfA[CHUNK], sfB[CHUNK], sfC[CHUNK];
    __shared__ float sprod[8][2][32];
    __shared__ int swarp[16];

    int tid  = threadIdx.x;
    int warp = tid >> 5, lane = tid & 31;
    int bx = blockIdx.x & 31, by = blockIdx.x >> 5;
    int stile = (by >> 2) * 8 + (bx >> 2);
    int supn = g_supercount[stile];

    if (supn == 0) {                       // empty sky tile
        if (tid < 64) {
            int cpg = tid >> 5, cl = tid & 31;
            g_si[(by * 8 + cpg * 4 + (cl >> 3)) * RS + bx * 8 + (cl & 7)] = 0.f;
        }
        return;
    }

    float tcx = (float)(bx * 8 + 4);
    float tcy = (float)(by * 8 + 4);

    int pg    = warp & 1;     // pixel group: rows 0-3 vs 4-7
    int slice = warp >> 1;    // face slice 0..7
    float px = (float)(bx * 8 + (lane & 7)) + 0.5f;
    float py = (float)(by * 8 + pg * 4 + (lane >> 3)) + 0.5f;

    const unsigned short* sup = g_superlist[stile];
    float prod = 1.f;
    const float KEXP = 2.8853900817779268f;  // 2 * log2(e)

    for (int cbase = 0; cbase < supn; cbase += CHUNK) {
        int cn = min(CHUNK, supn - cbase);

        // ---- cull this chunk (one face per thread) ----
        bool keep = false;
        float4 E0, E1, E2;
        if (tid < cn) {
            int f = (int)sup[cbase + tid];
            E0 = g_face[f * 3 + 0];
            E1 = g_face[f * 3 + 1];
            E2 = g_face[f * 3 + 2];
            float m0 = fmaf(E0.x, tcx, fmaf(E0.y, tcy, E0.z)) + 3.5f * (fabsf(E0.x) + fabsf(E0.y));
            float m1 = fmaf(E1.x, tcx, fmaf(E1.y, tcy, E1.z)) + 3.5f * (fabsf(E1.x) + fabsf(E1.y));
            float m2 = fmaf(E2.x, tcx, fmaf(E2.y, tcy, E2.z)) + 3.5f * (fabsf(E2.x) + fabsf(E2.y));
            keep = (m0 >= THRESH) && (m1 >= THRESH) && (m2 >= THRESH);
        }
        unsigned b = __ballot_sync(0xffffffffu, keep);
        if (lane == 0) swarp[warp] = __popc(b);
        __syncthreads();
        int base = 0, nlist = 0;
        #pragma unroll
        for (int w = 0; w < 16; w++) {
            int c = swarp[w];
            base  += (w < warp) ? c : 0;
            nlist += c;
        }
        if (keep) {
            int pos = base + __popc(b & ((1u << lane) - 1u));
            sfA[pos] = E0;
            sfB[pos] = E1;
            sfC[pos] = E2;
        }
        __syncthreads();

        // ---- raster this chunk's compacted faces ----
        int s0 = (nlist * slice) >> 3;
        int s1 = (nlist * (slice + 1)) >> 3;
        for (int i = s0; i < s1; i++) {
            float4 F0 = sfA[i], F1 = sfB[i], F2 = sfC[i];
            float d0 = fmaf(F0.y, py, fmaf(F0.x, px, F0.z));
            float d1 = fmaf(F1.y, py, fmaf(F1.x, px, F1.z));
            float d2 = fmaf(F2.y, py, fmaf(F2.x, px, F2.z));
            float dmin = fminf(d0, fminf(d1, d2));
            bool active = (dmin > THRESH) && (prod != 0.f);
            if (__any_sync(0xffffffffu, active)) {
                if (active) {
                    float t, rc;
                    asm("ex2.approx.ftz.f32 %0, %1;" : "=f"(t) : "f"(dmin * KEXP));
                    float den = 1.f + t;
                    asm("rcp.approx.ftz.f32 %0, %1;" : "=f"(rc) : "f"(den));
                    prod *= fmaxf(rc, 1e-6f);
                }
            }
            if (((i & 7) == 7) && __all_sync(0xffffffffu, prod == 0.f)) break;
        }

        // ---- CTA-wide absorbing-zero break ----
        bool wz = __all_sync(0xffffffffu, prod == 0.f);
        if (lane == 0) swarp[warp] = wz ? 1 : 0;
        __syncthreads();
        int dead0 = 0, dead1 = 0;
        #pragma unroll
        for (int w = 0; w < 16; w++) {
            if (swarp[w]) { if (w & 1) dead1 = 1; else dead0 = 1; }
        }
        __syncthreads();   // protect swarp reuse next chunk
        if (dead0 && dead1) break;   // every pixel already exactly 0 -> si=1
    }
    sprod[slice][pg][lane] = prod;
    __syncthreads();

    // ---- combine slice partials in ascending slice order ----
    if (tid < 64) {
        int cpg = tid >> 5;
        int cl  = tid & 31;
        float p = sprod[0][cpg][cl];
        #pragma unroll
        for (int s = 1; s < 8; s++) p *= sprod[s][cpg][cl];
        int cx = bx * 8 + (cl & 7);
        int cy = by * 8 + cpg * 4 + (cl >> 3);
        g_si[cy * RS + cx] = 1.f - p;
    }
}

// ---------------------------------------------------------------------------
// Kernel 4: nearest upsample 256->640, crop, write si, partial SSE
// ---------------------------------------------------------------------------
__global__ __launch_bounds__(256) void finalize_kernel(const float* __restrict__ mask,
                                                       float* __restrict__ out,
                                                       int si_offset) {
    int idx = blockIdx.x * 256 + threadIdx.x;
    int r = idx / IMGW;
    int c = idx - r * IMGW;
    int sr = (2 * r + 1) / 5;
    int sc = (2 * c + 1) / 5;
    float si = g_si[sr * RS + sc];
    out[idx + si_offset] = si;
    float d = si - mask[idx];
    float sq = d * d;

    __shared__ float red[8];
    #pragma unroll
    for (int o = 16; o > 0; o >>= 1)
        sq += __shfl_down_sync(0xffffffffu, sq, o);
    int warp = threadIdx.x >> 5, lane = threadIdx.x & 31;
    if (lane == 0) red[warp] = sq;
    __syncthreads();
    if (threadIdx.x == 0) {
        float s = 0.f;
        #pragma unroll
        for (int w = 0; w < 8; w++) s += red[w];
        g_partial[blockIdx.x] = s;
    }
}

__global__ __launch_bounds__(256) void loss_kernel(float* __restrict__ out) {
    int tid = threadIdx.x;
    float s = 0.f;
    for (int i = tid; i < NBLK; i += 256) s += g_partial[i];
    __shared__ float red[256];
    red[tid] = s;
    __syncthreads();
    #pragma unroll
    for (int o = 128; o > 0; o >>= 1) {
        if (tid < o) red[tid] += red[tid + o];
        __syncthreads();
    }
    if (tid == 0) out[0] = red[0];
}

// ---------------------------------------------------------------------------
extern "C" void kernel_launch(void* const* d_in, const int* in_sizes, int n_in,
                              void* d_out, int out_size) {
    const float* dof   = (const float*)d_in[0];
    const float* verts = (const float*)d_in[1];
    const int*   faces = (const int*)d_in[2];
    const float* K     = (const float*)d_in[3];
    const float* mask  = (const float*)d_in[4];
    float* out = (float*)d_out;

    int has_loss = (out_size >= NPIX + 1) ? 1 : 0;

    setup_face_kernel<<<1, 512>>>(dof, verts, K, faces);
    supercull_kernel<<<NSUPER, 256>>>();
    raster_kernel<<<1024, RT>>>();
    finalize_kernel<<<NBLK, 256>>>(mask, out, has_loss);
    if (has_loss) loss_kernel<<<1, 256>>>(out);
}

// round 7
// speedup vs baseline: 3.3488x; 1.0465x over previous
#include <cuda_runtime.h>
#include <cstdint>

#define RS 256
#define NV 2048
#define NF 4096
#define IMGH 480
#define IMGW 640
#define NPIX (IMGH * IMGW)
#define NBLK (NPIX / 256)
#define THRESH (-10.0f)
#define NSUPER 64          // 8x8 super-tiles of 32x32 px
#define RT 512             // raster CTA threads
#define CHUNK 512          // faces per cull/raster round
#define NHALF 2            // face-range splits per tile

__device__ float4 g_face[NF * 3];
__device__ float  g_prod[NHALF * RS * RS];
__device__ float  g_partial[NBLK];
__device__ unsigned short g_superlist[NSUPER][NF];
__device__ int    g_supercount[NSUPER];

// ---------------------------------------------------------------------------
// Kernel 1: fused se3_exp + vertex transform + projection + face coefficients
// ---------------------------------------------------------------------------
__global__ __launch_bounds__(512) void setup_face_kernel(
        const float* __restrict__ dof,
        const float* __restrict__ verts,
        const float* __restrict__ Kin,
        const int*   __restrict__ faces) {
    __shared__ float2 sxy[NV];
    __shared__ float sR[9], sT[3], sK[9];
    int tid = threadIdx.x;
    if (tid == 0) {
        float v0 = dof[0], v1 = dof[1], v2 = dof[2];
        float w0 = dof[3], w1 = dof[4], w2 = dof[5];
        float th2 = w0 * w0 + w1 * w1 + w2 * w2;
        float th  = sqrtf(th2 + 1e-30f);
        bool small = th < 1e-4f;
        float th_s  = small ? 1.f : th;
        float th2_s = small ? 1.f : th2;
        float A = small ? (1.f - th2 / 6.f)   : (sinf(th_s) / th_s);
        float B = small ? (0.5f - th2 / 24.f) : ((1.f - cosf(th_s)) / th2_s);
        float C = small ? (1.f / 6.f - th2 / 120.f)
                        : ((th_s - sinf(th_s)) / (th2_s * th_s));
        float Kx[9] = {0.f, -w2,  w1,
                       w2,  0.f, -w0,
                      -w1,  w0,  0.f};
        float K2[9];
        #pragma unroll
        for (int r = 0; r < 3; r++)
            #pragma unroll
            for (int c = 0; c < 3; c++) {
                float acc = 0.f;
                #pragma unroll
                for (int k = 0; k < 3; k++) acc += Kx[r * 3 + k] * Kx[k * 3 + c];
                K2[r * 3 + c] = acc;
            }
        float V[9];
        #pragma unroll
        for (int i = 0; i < 9; i++) {
            float I = (i == 0 || i == 4 || i == 8) ? 1.f : 0.f;
            sR[i] = I + A * Kx[i] + B * K2[i];
            V[i]  = I + B * Kx[i] + C * K2[i];
        }
        sT[0] = V[0] * v0 + V[1] * v1 + V[2] * v2;
        sT[1] = V[3] * v0 + V[4] * v1 + V[5] * v2;
        sT[2] = V[6] * v0 + V[7] * v1 + V[8] * v2;
    }
    if (tid < 9) sK[tid] = Kin[tid];
    __syncthreads();
    for (int i = tid; i < NV; i += 512) {
        float x = verts[3 * i + 0], y = verts[3 * i + 1], z = verts[3 * i + 2];
        float cx = sR[0] * x + sR[1] * y + sR[2] * z + sT[0];
        float cy = sR[3] * x + sR[4] * y + sR[5] * z + sT[1];
        float cz = sR[6] * x + sR[7] * y + sR[8] * z + sT[2];
        float u = sK[0] * cx + sK[1] * cy + sK[2] * cz;
        float v = sK[3] * cx + sK[4] * cy + sK[5] * cz;
        float w = sK[6] * cx + sK[7] * cy + sK[8] * cz;
        sxy[i] = make_float2((u / w) * 0.4f, (v / w) * 0.4f);
    }
    __syncthreads();
    for (int f = tid; f < NF; f += 512) {
        int i0 = faces[3 * f + 0];
        int i1 = faces[3 * f + 1];
        int i2 = faces[3 * f + 2];
        float2 p0 = sxy[i0], p1 = sxy[i1], p2 = sxy[i2];
        float2 e[3];
        e[0] = make_float2(p1.x - p0.x, p1.y - p0.y);
        e[1] = make_float2(p2.x - p1.x, p2.y - p1.y);
        e[2] = make_float2(p0.x - p2.x, p0.y - p2.y);
        float2 a[3] = {p0, p1, p2};
        float area2 = e[0].y * e[2].x - e[0].x * e[2].y;
        float sgn = (area2 >= 0.f) ? 1.f : -1.f;
        #pragma unroll
        for (int k = 0; k < 3; k++) {
            float elen = sqrtf(e[k].x * e[k].x + e[k].y * e[k].y) + 1e-9f;
            float s = sgn / elen;
            float c0 = e[k].x * a[k].y - e[k].y * a[k].x;
            g_face[f * 3 + k] = make_float4(-s * e[k].y, s * e[k].x, -s * c0, 0.f);
        }
    }
}

// ---------------------------------------------------------------------------
// Kernel 2: super-tile cull (32x32 px), ordered compaction into global list.
// ---------------------------------------------------------------------------
__global__ __launch_bounds__(256) void supercull_kernel() {
    __shared__ int swarp[8];
    __shared__ int scount;
    int tid  = threadIdx.x;
    int warp = tid >> 5, lane = tid & 31;
    int sx = blockIdx.x & 7, sy = blockIdx.x >> 3;
    float tcx = (float)(sx * 32 + 16);
    float tcy = (float)(sy * 32 + 16);

    if (tid == 0) scount = 0;
    __syncthreads();

    for (int r = 0; r < NF / 256; r++) {
        int f = r * 256 + tid;
        float4 E0 = g_face[f * 3 + 0];
        float4 E1 = g_face[f * 3 + 1];
        float4 E2 = g_face[f * 3 + 2];
        float m0 = fmaf(E0.x, tcx, fmaf(E0.y, tcy, E0.z)) + 15.5f * (fabsf(E0.x) + fabsf(E0.y));
        float m1 = fmaf(E1.x, tcx, fmaf(E1.y, tcy, E1.z)) + 15.5f * (fabsf(E1.x) + fabsf(E1.y));
        float m2 = fmaf(E2.x, tcx, fmaf(E2.y, tcy, E2.z)) + 15.5f * (fabsf(E2.x) + fabsf(E2.y));
        bool keep = (m0 >= THRESH) && (m1 >= THRESH) && (m2 >= THRESH);

        unsigned b = __ballot_sync(0xffffffffu, keep);
        if (lane == 0) swarp[warp] = __popc(b);
        __syncthreads();
        int base = scount;
        #pragma unroll
        for (int w = 0; w < 8; w++) base += (w < warp) ? swarp[w] : 0;
        if (keep)
            g_superlist[blockIdx.x][base + __popc(b & ((1u << lane) - 1u))] = (unsigned short)f;
        __syncthreads();
        if (tid == 0) {
            int tot = 0;
            #pragma unroll
            for (int w = 0; w < 8; w++) tot += swarp[w];
            scount += tot;
        }
        __syncthreads();
    }
    if (tid == 0) g_supercount[blockIdx.x] = scount;
}

// ---------------------------------------------------------------------------
// Kernel 3: rasterizer, 8x8 px tiles, 2048 CTAs x 512 threads.
// CTA = (tile, half): processes half of the tile's super-list range.
// Chunked: cull 512 faces -> compacted smem stage -> 16 warps (8 slices x
// 2 pixel-groups) raster -> CTA-wide absorbing-zero break.
// Writes per-half pixel product; finalize combines the two halves.
// ---------------------------------------------------------------------------
__global__ __launch_bounds__(RT) void raster_kernel() {
    __shared__ float4 sfA[CHUNK], sfB[CHUNK], sfC[CHUNK];
    __shared__ float sprod[8][2][32];
    __shared__ int swarp[16];

    int tid  = threadIdx.x;
    int warp = tid >> 5, lane = tid & 31;
    int tix  = blockIdx.x & 1023;
    int half = blockIdx.x >> 10;
    int bx = tix & 31, by = tix >> 5;
    int stile = (by >> 2) * 8 + (bx >> 2);
    int supn = g_supercount[stile];

    float* prodout = g_prod + half * (RS * RS);

    if (supn == 0) {                       // empty sky tile
        if (tid < 64) {
            int cpg = tid >> 5, cl = tid & 31;
            prodout[(by * 8 + cpg * 4 + (cl >> 3)) * RS + bx * 8 + (cl & 7)] = 1.f;
        }
        return;
    }

    // this CTA's face range within the super-list
    int r0 = (supn * half) / NHALF;
    int r1 = (supn * (half + 1)) / NHALF;

    float tcx = (float)(bx * 8 + 4);
    float tcy = (float)(by * 8 + 4);

    int pg    = warp & 1;     // pixel group: rows 0-3 vs 4-7
    int slice = warp >> 1;    // face slice 0..7
    float px = (float)(bx * 8 + (lane & 7)) + 0.5f;
    float py = (float)(by * 8 + pg * 4 + (lane >> 3)) + 0.5f;

    const unsigned short* sup = g_superlist[stile];
    float prod = 1.f;
    const float KEXP = 2.8853900817779268f;  // 2 * log2(e)

    for (int cbase = r0; cbase < r1; cbase += CHUNK) {
        int cn = min(CHUNK, r1 - cbase);

        // ---- cull this chunk (one face per thread) ----
        bool keep = false;
        float4 E0, E1, E2;
        if (tid < cn) {
            int f = (int)sup[cbase + tid];
            E0 = g_face[f * 3 + 0];
            E1 = g_face[f * 3 + 1];
            E2 = g_face[f * 3 + 2];
            float m0 = fmaf(E0.x, tcx, fmaf(E0.y, tcy, E0.z)) + 3.5f * (fabsf(E0.x) + fabsf(E0.y));
            float m1 = fmaf(E1.x, tcx, fmaf(E1.y, tcy, E1.z)) + 3.5f * (fabsf(E1.x) + fabsf(E1.y));
            float m2 = fmaf(E2.x, tcx, fmaf(E2.y, tcy, E2.z)) + 3.5f * (fabsf(E2.x) + fabsf(E2.y));
            keep = (m0 >= THRESH) && (m1 >= THRESH) && (m2 >= THRESH);
        }
        unsigned b = __ballot_sync(0xffffffffu, keep);
        if (lane == 0) swarp[warp] = __popc(b);
        __syncthreads();
        int base = 0, nlist = 0;
        #pragma unroll
        for (int w = 0; w < 16; w++) {
            int c = swarp[w];
            base  += (w < warp) ? c : 0;
            nlist += c;
        }
        if (keep) {
            int pos = base + __popc(b & ((1u << lane) - 1u));
            sfA[pos] = E0;
            sfB[pos] = E1;
            sfC[pos] = E2;
        }
        __syncthreads();

        // ---- raster this chunk's compacted faces ----
        int s0 = (nlist * slice) >> 3;
        int s1 = (nlist * (slice + 1)) >> 3;
        for (int i = s0; i < s1; i++) {
            float4 F0 = sfA[i], F1 = sfB[i], F2 = sfC[i];
            float d0 = fmaf(F0.y, py, fmaf(F0.x, px, F0.z));
            float d1 = fmaf(F1.y, py, fmaf(F1.x, px, F1.z));
            float d2 = fmaf(F2.y, py, fmaf(F2.x, px, F2.z));
            float dmin = fminf(d0, fminf(d1, d2));
            bool active = (dmin > THRESH) && (prod != 0.f);
            if (__any_sync(0xffffffffu, active)) {
                if (active) {
                    float t, rc;
                    asm("ex2.approx.ftz.f32 %0, %1;" : "=f"(t) : "f"(dmin * KEXP));
                    float den = 1.f + t;
                    asm("rcp.approx.ftz.f32 %0, %1;" : "=f"(rc) : "f"(den));
                    prod *= fmaxf(rc, 1e-6f);
                }
            }
            if (((i & 7) == 7) && __all_sync(0xffffffffu, prod == 0.f)) break;
        }

        // ---- CTA-wide absorbing-zero break ----
        bool wz = __all_sync(0xffffffffu, prod == 0.f);
        if (lane == 0) swarp[warp] = wz ? 1 : 0;
        __syncthreads();
        int alldead = 1;
        #pragma unroll
        for (int w = 0; w < 16; w++) alldead &= swarp[w];
        __syncthreads();   // protect swarp reuse next chunk
        if (alldead) break;   // every pixel of this half already exactly 0
    }
    sprod[slice][pg][lane] = prod;
    __syncthreads();

    // ---- combine slice partials in ascending slice order ----
    if (tid < 64) {
        int cpg = tid >> 5;
        int cl  = tid & 31;
        float p = sprod[0][cpg][cl];
        #pragma unroll
        for (int s = 1; s < 8; s++) p *= sprod[s][cpg][cl];
        int cx = bx * 8 + (cl & 7);
        int cy = by * 8 + cpg * 4 + (cl >> 3);
        prodout[cy * RS + cx] = p;
    }
}

// ---------------------------------------------------------------------------
// Kernel 4: combine halves, nearest upsample 256->640, crop, si, partial SSE
// ---------------------------------------------------------------------------
__global__ __launch_bounds__(256) void finalize_kernel(const float* __restrict__ mask,
                                                       float* __restrict__ out,
                                                       int si_offset) {
    int idx = blockIdx.x * 256 + threadIdx.x;
    int r = idx / IMGW;
    int c = idx - r * IMGW;
    int sr = (2 * r + 1) / 5;
    int sc = (2 * c + 1) / 5;
    int p = sr * RS + sc;
    float si = 1.f - g_prod[p] * g_prod[RS * RS + p];
    out[idx + si_offset] = si;
    float d = si - mask[idx];
    float sq = d * d;

    __shared__ float red[8];
    #pragma unroll
    for (int o = 16; o > 0; o >>= 1)
        sq += __shfl_down_sync(0xffffffffu, sq, o);
    int warp = threadIdx.x >> 5, lane = threadIdx.x & 31;
    if (lane == 0) red[warp] = sq;
    __syncthreads();
    if (threadIdx.x == 0) {
        float s = 0.f;
        #pragma unroll
        for (int w = 0; w < 8; w++) s += red[w];
        g_partial[blockIdx.x] = s;
    }
}

__global__ __launch_bounds__(256) void loss_kernel(float* __restrict__ out) {
    int tid = threadIdx.x;
    float s = 0.f;
    for (int i = tid; i < NBLK; i += 256) s += g_partial[i];
    __shared__ float red[256];
    red[tid] = s;
    __syncthreads();
    #pragma unroll
    for (int o = 128; o > 0; o >>= 1) {
        if (tid < o) red[tid] += red[tid + o];
        __syncthreads();
    }
    if (tid == 0) out[0] = red[0];
}

// ---------------------------------------------------------------------------
extern "C" void kernel_launch(void* const* d_in, const int* in_sizes, int n_in,
                              void* d_out, int out_size) {
    const float* dof   = (const float*)d_in[0];
    const float* verts = (const float*)d_in[1];
    const int*   faces = (const int*)d_in[2];
    const float* K     = (const float*)d_in[3];
    const float* mask  = (const float*)d_in[4];
    float* out = (float*)d_out;

    int has_loss = (out_size >= NPIX + 1) ? 1 : 0;

    setup_face_kernel<<<1, 512>>>(dof, verts, K, faces);
    supercull_kernel<<<NSUPER, 256>>>();
    raster_kernel<<<1024 * NHALF, RT>>>();
    finalize_kernel<<<NBLK, 256>>>(mask, out, has_loss);
    if (has_loss) loss_kernel<<<1, 256>>>(out);
}

// round 8
// speedup vs baseline: 3.7625x; 1.1235x over previous
#include <cuda_runtime.h>
#include <cstdint>

#define RS 256
#define NV 2048
#define NF 4096
#define IMGH 480
#define IMGW 640
#define NPIX (IMGH * IMGW)
#define NBLK (NPIX / 256)
#define THRESH (-10.0f)
#define NSUPER 64          // 8x8 super-tiles of 32x32 px
#define RT 512             // raster CTA threads
#define CHUNK 512          // faces per cull/raster round
#define NHALF 2            // face-range splits per tile

__device__ float4 g_face[NF * 3];
__device__ float  g_prod[NHALF * RS * RS];
__device__ float  g_partial[NBLK];
__device__ unsigned short g_superlist[NSUPER][NF];
__device__ int    g_supercount[NSUPER];

// ---------------------------------------------------------------------------
// Kernel 1: fused se3_exp + vertex transform + projection + face coefficients
// 4 CTAs: each redundantly transforms verts (cheap), builds NF/4 faces.
// ---------------------------------------------------------------------------
__global__ __launch_bounds__(512) void setup_face_kernel(
        const float* __restrict__ dof,
        const float* __restrict__ verts,
        const float* __restrict__ Kin,
        const int*   __restrict__ faces) {
    __shared__ float2 sxy[NV];
    __shared__ float sR[9], sT[3], sK[9];
    int tid = threadIdx.x;
    if (tid == 0) {
        float v0 = dof[0], v1 = dof[1], v2 = dof[2];
        float w0 = dof[3], w1 = dof[4], w2 = dof[5];
        float th2 = w0 * w0 + w1 * w1 + w2 * w2;
        float th  = sqrtf(th2 + 1e-30f);
        bool small = th < 1e-4f;
        float th_s  = small ? 1.f : th;
        float th2_s = small ? 1.f : th2;
        float A = small ? (1.f - th2 / 6.f)   : (sinf(th_s) / th_s);
        float B = small ? (0.5f - th2 / 24.f) : ((1.f - cosf(th_s)) / th2_s);
        float C = small ? (1.f / 6.f - th2 / 120.f)
                        : ((th_s - sinf(th_s)) / (th2_s * th_s));
        float Kx[9] = {0.f, -w2,  w1,
                       w2,  0.f, -w0,
                      -w1,  w0,  0.f};
        float K2[9];
        #pragma unroll
        for (int r = 0; r < 3; r++)
            #pragma unroll
            for (int c = 0; c < 3; c++) {
                float acc = 0.f;
                #pragma unroll
                for (int k = 0; k < 3; k++) acc += Kx[r * 3 + k] * Kx[k * 3 + c];
                K2[r * 3 + c] = acc;
            }
        float V[9];
        #pragma unroll
        for (int i = 0; i < 9; i++) {
            float I = (i == 0 || i == 4 || i == 8) ? 1.f : 0.f;
            sR[i] = I + A * Kx[i] + B * K2[i];
            V[i]  = I + B * Kx[i] + C * K2[i];
        }
        sT[0] = V[0] * v0 + V[1] * v1 + V[2] * v2;
        sT[1] = V[3] * v0 + V[4] * v1 + V[5] * v2;
        sT[2] = V[6] * v0 + V[7] * v1 + V[8] * v2;
    }
    if (tid < 9) sK[tid] = Kin[tid];
    __syncthreads();
    for (int i = tid; i < NV; i += 512) {
        float x = verts[3 * i + 0], y = verts[3 * i + 1], z = verts[3 * i + 2];
        float cx = sR[0] * x + sR[1] * y + sR[2] * z + sT[0];
        float cy = sR[3] * x + sR[4] * y + sR[5] * z + sT[1];
        float cz = sR[6] * x + sR[7] * y + sR[8] * z + sT[2];
        float u = sK[0] * cx + sK[1] * cy + sK[2] * cz;
        float v = sK[3] * cx + sK[4] * cy + sK[5] * cz;
        float w = sK[6] * cx + sK[7] * cy + sK[8] * cz;
        sxy[i] = make_float2((u / w) * 0.4f, (v / w) * 0.4f);
    }
    __syncthreads();
    int fbase = blockIdx.x * (NF / 4);
    for (int f = fbase + tid; f < fbase + NF / 4; f += 512) {
        int i0 = faces[3 * f + 0];
        int i1 = faces[3 * f + 1];
        int i2 = faces[3 * f + 2];
        float2 p0 = sxy[i0], p1 = sxy[i1], p2 = sxy[i2];
        float2 e[3];
        e[0] = make_float2(p1.x - p0.x, p1.y - p0.y);
        e[1] = make_float2(p2.x - p1.x, p2.y - p1.y);
        e[2] = make_float2(p0.x - p2.x, p0.y - p2.y);
        float2 a[3] = {p0, p1, p2};
        float area2 = e[0].y * e[2].x - e[0].x * e[2].y;
        float sgn = (area2 >= 0.f) ? 1.f : -1.f;
        #pragma unroll
        for (int k = 0; k < 3; k++) {
            float elen = sqrtf(e[k].x * e[k].x + e[k].y * e[k].y) + 1e-9f;
            float s = sgn / elen;
            float c0 = e[k].x * a[k].y - e[k].y * a[k].x;
            g_face[f * 3 + k] = make_float4(-s * e[k].y, s * e[k].x, -s * c0, 0.f);
        }
    }
}

// ---------------------------------------------------------------------------
// Kernel 2: super-tile cull (32x32 px), ordered compaction into global list.
// ---------------------------------------------------------------------------
__global__ __launch_bounds__(256) void supercull_kernel() {
    __shared__ int swarp[8];
    __shared__ int scount;
    int tid  = threadIdx.x;
    int warp = tid >> 5, lane = tid & 31;
    int sx = blockIdx.x & 7, sy = blockIdx.x >> 3;
    float tcx = (float)(sx * 32 + 16);
    float tcy = (float)(sy * 32 + 16);

    if (tid == 0) scount = 0;
    __syncthreads();

    for (int r = 0; r < NF / 256; r++) {
        int f = r * 256 + tid;
        float4 E0 = g_face[f * 3 + 0];
        float4 E1 = g_face[f * 3 + 1];
        float4 E2 = g_face[f * 3 + 2];
        float m0 = fmaf(E0.x, tcx, fmaf(E0.y, tcy, E0.z)) + 15.5f * (fabsf(E0.x) + fabsf(E0.y));
        float m1 = fmaf(E1.x, tcx, fmaf(E1.y, tcy, E1.z)) + 15.5f * (fabsf(E1.x) + fabsf(E1.y));
        float m2 = fmaf(E2.x, tcx, fmaf(E2.y, tcy, E2.z)) + 15.5f * (fabsf(E2.x) + fabsf(E2.y));
        bool keep = (m0 >= THRESH) && (m1 >= THRESH) && (m2 >= THRESH);

        unsigned b = __ballot_sync(0xffffffffu, keep);
        if (lane == 0) swarp[warp] = __popc(b);
        __syncthreads();
        int base = scount;
        #pragma unroll
        for (int w = 0; w < 8; w++) base += (w < warp) ? swarp[w] : 0;
        if (keep)
            g_superlist[blockIdx.x][base + __popc(b & ((1u << lane) - 1u))] = (unsigned short)f;
        __syncthreads();
        if (tid == 0) {
            int tot = 0;
            #pragma unroll
            for (int w = 0; w < 8; w++) tot += swarp[w];
            scount += tot;
        }
        __syncthreads();
    }
    if (tid == 0) g_supercount[blockIdx.x] = scount;
}

// ---------------------------------------------------------------------------
// Kernel 3: rasterizer, 8x8 px tiles, 2048 CTAs x 512 threads.
// CTA = (tile, half). 16 warps = 16 face slices; each thread owns 2 pixels
// (x, y) and (x, y+4) -> second row's distances via d + 4Q (1 extra FMA/edge).
// Chunked: cull 512 -> smem stage -> raster -> CTA-wide absorbing break.
// ---------------------------------------------------------------------------
__global__ __launch_bounds__(RT) void raster_kernel() {
    __shared__ float4 sfA[CHUNK], sfB[CHUNK], sfC[CHUNK];
    __shared__ float sprodA[16][32];
    __shared__ float sprodB[16][32];
    __shared__ int swarp[16];

    int tid  = threadIdx.x;
    int warp = tid >> 5, lane = tid & 31;
    int tix  = blockIdx.x & 1023;
    int half = blockIdx.x >> 10;
    int bx = tix & 31, by = tix >> 5;
    int stile = (by >> 2) * 8 + (bx >> 2);
    int supn = g_supercount[stile];

    float* prodout = g_prod + half * (RS * RS);

    int x  = bx * 8 + (lane & 7);
    int yA = by * 8 + (lane >> 3);        // rows 0..3
    // row B = yA + 4                      // rows 4..7

    if (supn == 0) {                       // empty sky tile
        if (tid < 32) {
            prodout[yA * RS + x] = 1.f;
            prodout[(yA + 4) * RS + x] = 1.f;
        }
        return;
    }

    int r0 = (supn * half) / NHALF;
    int r1 = (supn * (half + 1)) / NHALF;

    float tcx = (float)(bx * 8 + 4);
    float tcy = (float)(by * 8 + 4);

    float px  = (float)x + 0.5f;
    float pyA = (float)yA + 0.5f;

    const unsigned short* sup = g_superlist[stile];
    float prodA = 1.f, prodB = 1.f;
    const float KEXP = 2.8853900817779268f;  // 2 * log2(e)

    for (int cbase = r0; cbase < r1; cbase += CHUNK) {
        int cn = min(CHUNK, r1 - cbase);

        // ---- cull this chunk (one face per thread) ----
        bool keep = false;
        float4 E0, E1, E2;
        if (tid < cn) {
            int f = (int)sup[cbase + tid];
            E0 = g_face[f * 3 + 0];
            E1 = g_face[f * 3 + 1];
            E2 = g_face[f * 3 + 2];
            float m0 = fmaf(E0.x, tcx, fmaf(E0.y, tcy, E0.z)) + 3.5f * (fabsf(E0.x) + fabsf(E0.y));
            float m1 = fmaf(E1.x, tcx, fmaf(E1.y, tcy, E1.z)) + 3.5f * (fabsf(E1.x) + fabsf(E1.y));
            float m2 = fmaf(E2.x, tcx, fmaf(E2.y, tcy, E2.z)) + 3.5f * (fabsf(E2.x) + fabsf(E2.y));
            keep = (m0 >= THRESH) && (m1 >= THRESH) && (m2 >= THRESH);
        }
        unsigned b = __ballot_sync(0xffffffffu, keep);
        if (lane == 0) swarp[warp] = __popc(b);
        __syncthreads();
        int base = 0, nlist = 0;
        #pragma unroll
        for (int w = 0; w < 16; w++) {
            int c = swarp[w];
            base  += (w < warp) ? c : 0;
            nlist += c;
        }
        if (keep) {
            int pos = base + __popc(b & ((1u << lane) - 1u));
            sfA[pos] = E0;
            sfB[pos] = E1;
            sfC[pos] = E2;
        }
        __syncthreads();

        // ---- raster this chunk's compacted faces, slice = warp ----
        int s0 = (nlist * warp) >> 4;
        int s1 = (nlist * (warp + 1)) >> 4;
        for (int i = s0; i < s1; i++) {
            float4 F0 = sfA[i], F1 = sfB[i], F2 = sfC[i];
            float d0 = fmaf(F0.y, pyA, fmaf(F0.x, px, F0.z));
            float d1 = fmaf(F1.y, pyA, fmaf(F1.x, px, F1.z));
            float d2 = fmaf(F2.y, pyA, fmaf(F2.x, px, F2.z));
            float e0 = fmaf(4.f, F0.y, d0);
            float e1 = fmaf(4.f, F1.y, d1);
            float e2 = fmaf(4.f, F2.y, d2);
            float dminA = fminf(d0, fminf(d1, d2));
            float dminB = fminf(e0, fminf(e1, e2));
            bool actA = (dminA > THRESH) && (prodA != 0.f);
            bool actB = (dminB > THRESH) && (prodB != 0.f);
            if (__any_sync(0xffffffffu, actA || actB)) {
                if (actA) {
                    float t, rc;
                    asm("ex2.approx.ftz.f32 %0, %1;" : "=f"(t) : "f"(dminA * KEXP));
                    float den = 1.f + t;
                    asm("rcp.approx.ftz.f32 %0, %1;" : "=f"(rc) : "f"(den));
                    prodA *= fmaxf(rc, 1e-6f);
                }
                if (actB) {
                    float t, rc;
                    asm("ex2.approx.ftz.f32 %0, %1;" : "=f"(t) : "f"(dminB * KEXP));
                    float den = 1.f + t;
                    asm("rcp.approx.ftz.f32 %0, %1;" : "=f"(rc) : "f"(den));
                    prodB *= fmaxf(rc, 1e-6f);
                }
            }
            if (((i & 7) == 7) &&
                __all_sync(0xffffffffu, (prodA == 0.f) && (prodB == 0.f))) break;
        }

        // ---- CTA-wide absorbing-zero break ----
        bool wz = __all_sync(0xffffffffu, (prodA == 0.f) && (prodB == 0.f));
        if (lane == 0) swarp[warp] = wz ? 1 : 0;
        __syncthreads();
        int alldead = 1;
        #pragma unroll
        for (int w = 0; w < 16; w++) alldead &= swarp[w];
        __syncthreads();   // protect swarp reuse next chunk
        if (alldead) break;
    }
    sprodA[warp][lane] = prodA;
    sprodB[warp][lane] = prodB;
    __syncthreads();

    // ---- combine 16 slice partials per pixel in ascending slice order ----
    if (tid < 32) {
        float pA = sprodA[0][tid];
        float pB = sprodB[0][tid];
        #pragma unroll
        for (int s = 1; s < 16; s++) {
            pA *= sprodA[s][tid];
            pB *= sprodB[s][tid];
        }
        prodout[yA * RS + x] = pA;
        prodout[(yA + 4) * RS + x] = pB;
    }
}

// ---------------------------------------------------------------------------
// Kernel 4: combine halves, nearest upsample 256->640, crop, si, partial SSE
// ---------------------------------------------------------------------------
__global__ __launch_bounds__(256) void finalize_kernel(const float* __restrict__ mask,
                                                       float* __restrict__ out,
                                                       int si_offset) {
    int idx = blockIdx.x * 256 + threadIdx.x;
    int r = idx / IMGW;
    int c = idx - r * IMGW;
    int sr = (2 * r + 1) / 5;
    int sc = (2 * c + 1) / 5;
    int p = sr * RS + sc;
    float si = 1.f - g_prod[p] * g_prod[RS * RS + p];
    out[idx + si_offset] = si;
    float d = si - mask[idx];
    float sq = d * d;

    __shared__ float red[8];
    #pragma unroll
    for (int o = 16; o > 0; o >>= 1)
        sq += __shfl_down_sync(0xffffffffu, sq, o);
    int warp = threadIdx.x >> 5, lane = threadIdx.x & 31;
    if (lane == 0) red[warp] = sq;
    __syncthreads();
    if (threadIdx.x == 0) {
        float s = 0.f;
        #pragma unroll
        for (int w = 0; w < 8; w++) s += red[w];
        g_partial[blockIdx.x] = s;
    }
}

__global__ __launch_bounds__(256) void loss_kernel(float* __restrict__ out) {
    int tid = threadIdx.x;
    float s = 0.f;
    for (int i = tid; i < NBLK; i += 256) s += g_partial[i];
    __shared__ float red[256];
    red[tid] = s;
    __syncthreads();
    #pragma unroll
    for (int o = 128; o > 0; o >>= 1) {
        if (tid < o) red[tid] += red[tid + o];
        __syncthreads();
    }
    if (tid == 0) out[0] = red[0];
}

// ---------------------------------------------------------------------------
extern "C" void kernel_launch(void* const* d_in, const int* in_sizes, int n_in,
                              void* d_out, int out_size) {
    const float* dof   = (const float*)d_in[0];
    const float* verts = (const float*)d_in[1];
    const int*   faces = (const int*)d_in[2];
    const float* K     = (const float*)d_in[3];
    const float* mask  = (const float*)d_in[4];
    float* out = (float*)d_out;

    int has_loss = (out_size >= NPIX + 1) ? 1 : 0;

    setup_face_kernel<<<4, 512>>>(dof, verts, K, faces);
    supercull_kernel<<<NSUPER, 256>>>();
    raster_kernel<<<1024 * NHALF, RT>>>();
    finalize_kernel<<<NBLK, 256>>>(mask, out, has_loss);
    if (has_loss) loss_kernel<<<1, 256>>>(out);
}

// round 10
// speedup vs baseline: 4.0358x; 1.0726x over previous
#include <cuda_runtime.h>
#include <cstdint>

#define RS 256
#define NV 2048
#define NF 4096
#define IMGH 480
#define IMGW 640
#define NPIX (IMGH * IMGW)
#define FBLK (NPIX / 1024)   // finalize blocks (4 px/thread)
#define THRESH (-10.0f)
#define NSUPER 64            // 8x8 super-tiles of 32x32 px
#define RT 512               // raster CTA threads
#define CHUNK 512            // faces per cull/raster round
#define NHALF 2              // face-range splits per tile
#define NTILE 512            // 16x8-px tiles: 16 x 32

__device__ float4 g_face[NF * 3];
__device__ float  g_prod[NHALF * RS * RS];
__device__ float  g_partial[FBLK];
__device__ unsigned short g_superlist[NSUPER][NF];
__device__ int    g_supercount[NSUPER];

// ---------------------------------------------------------------------------
// Kernel 1: fused se3_exp + vertex transform + projection + face coefficients
// 4 CTAs: each redundantly transforms verts (cheap), builds NF/4 faces.
// ---------------------------------------------------------------------------
__global__ __launch_bounds__(512) void setup_face_kernel(
        const float* __restrict__ dof,
        const float* __restrict__ verts,
        const float* __restrict__ Kin,
        const int*   __restrict__ faces) {
    __shared__ float2 sxy[NV];
    __shared__ float sR[9], sT[3], sK[9];
    int tid = threadIdx.x;
    if (tid == 0) {
        float v0 = dof[0], v1 = dof[1], v2 = dof[2];
        float w0 = dof[3], w1 = dof[4], w2 = dof[5];
        float th2 = w0 * w0 + w1 * w1 + w2 * w2;
        float th  = sqrtf(th2 + 1e-30f);
        bool small = th < 1e-4f;
        float th_s  = small ? 1.f : th;
        float th2_s = small ? 1.f : th2;
        float A = small ? (1.f - th2 / 6.f)   : (sinf(th_s) / th_s);
        float B = small ? (0.5f - th2 / 24.f) : ((1.f - cosf(th_s)) / th2_s);
        float C = small ? (1.f / 6.f - th2 / 120.f)
                        : ((th_s - sinf(th_s)) / (th2_s * th_s));
        float Kx[9] = {0.f, -w2,  w1,
                       w2,  0.f, -w0,
                      -w1,  w0,  0.f};
        float K2[9];
        #pragma unroll
        for (int r = 0; r < 3; r++)
            #pragma unroll
            for (int c = 0; c < 3; c++) {
                float acc = 0.f;
                #pragma unroll
                for (int k = 0; k < 3; k++) acc += Kx[r * 3 + k] * Kx[k * 3 + c];
                K2[r * 3 + c] = acc;
            }
        float V[9];
        #pragma unroll
        for (int i = 0; i < 9; i++) {
            float I = (i == 0 || i == 4 || i == 8) ? 1.f : 0.f;
            sR[i] = I + A * Kx[i] + B * K2[i];
            V[i]  = I + B * Kx[i] + C * K2[i];
        }
        sT[0] = V[0] * v0 + V[1] * v1 + V[2] * v2;
        sT[1] = V[3] * v0 + V[4] * v1 + V[5] * v2;
        sT[2] = V[6] * v0 + V[7] * v1 + V[8] * v2;
    }
    if (tid < 9) sK[tid] = Kin[tid];
    __syncthreads();
    for (int i = tid; i < NV; i += 512) {
        float x = verts[3 * i + 0], y = verts[3 * i + 1], z = verts[3 * i + 2];
        float cx = sR[0] * x + sR[1] * y + sR[2] * z + sT[0];
        float cy = sR[3] * x + sR[4] * y + sR[5] * z + sT[1];
        float cz = sR[6] * x + sR[7] * y + sR[8] * z + sT[2];
        float u = sK[0] * cx + sK[1] * cy + sK[2] * cz;
        float v = sK[3] * cx + sK[4] * cy + sK[5] * cz;
        float w = sK[6] * cx + sK[7] * cy + sK[8] * cz;
        sxy[i] = make_float2((u / w) * 0.4f, (v / w) * 0.4f);
    }
    __syncthreads();
    int fbase = blockIdx.x * (NF / 4);
    for (int f = fbase + tid; f < fbase + NF / 4; f += 512) {
        int i0 = faces[3 * f + 0];
        int i1 = faces[3 * f + 1];
        int i2 = faces[3 * f + 2];
        float2 p0 = sxy[i0], p1 = sxy[i1], p2 = sxy[i2];
        float2 e[3];
        e[0] = make_float2(p1.x - p0.x, p1.y - p0.y);
        e[1] = make_float2(p2.x - p1.x, p2.y - p1.y);
        e[2] = make_float2(p0.x - p2.x, p0.y - p2.y);
        float2 a[3] = {p0, p1, p2};
        float area2 = e[0].y * e[2].x - e[0].x * e[2].y;
        float sgn = (area2 >= 0.f) ? 1.f : -1.f;
        #pragma unroll
        for (int k = 0; k < 3; k++) {
            float elen = sqrtf(e[k].x * e[k].x + e[k].y * e[k].y) + 1e-9f;
            float s = sgn / elen;
            float c0 = e[k].x * a[k].y - e[k].y * a[k].x;
            g_face[f * 3 + k] = make_float4(-s * e[k].y, s * e[k].x, -s * c0, 0.f);
        }
    }
}

// ---------------------------------------------------------------------------
// Kernel 2: super-tile cull (32x32 px), ordered compaction, 512 threads.
// ---------------------------------------------------------------------------
__global__ __launch_bounds__(512) void supercull_kernel() {
    __shared__ int swarp[16];
    __shared__ int scount;
    int tid  = threadIdx.x;
    int warp = tid >> 5, lane = tid & 31;
    int sx = blockIdx.x & 7, sy = blockIdx.x >> 3;
    float tcx = (float)(sx * 32 + 16);
    float tcy = (float)(sy * 32 + 16);

    if (tid == 0) scount = 0;
    __syncthreads();

    for (int r = 0; r < NF / 512; r++) {
        int f = r * 512 + tid;
        float4 E0 = g_face[f * 3 + 0];
        float4 E1 = g_face[f * 3 + 1];
        float4 E2 = g_face[f * 3 + 2];
        float m0 = fmaf(E0.x, tcx, fmaf(E0.y, tcy, E0.z)) + 15.5f * (fabsf(E0.x) + fabsf(E0.y));
        float m1 = fmaf(E1.x, tcx, fmaf(E1.y, tcy, E1.z)) + 15.5f * (fabsf(E1.x) + fabsf(E1.y));
        float m2 = fmaf(E2.x, tcx, fmaf(E2.y, tcy, E2.z)) + 15.5f * (fabsf(E2.x) + fabsf(E2.y));
        bool keep = (m0 >= THRESH) && (m1 >= THRESH) && (m2 >= THRESH);

        unsigned b = __ballot_sync(0xffffffffu, keep);
        if (lane == 0) swarp[warp] = __popc(b);
        __syncthreads();
        int base = scount;
        #pragma unroll
        for (int w = 0; w < 16; w++) base += (w < warp) ? swarp[w] : 0;
        if (keep)
            g_superlist[blockIdx.x][base + __popc(b & ((1u << lane) - 1u))] = (unsigned short)f;
        __syncthreads();
        if (tid == 0) {
            int tot = 0;
            #pragma unroll
            for (int w = 0; w < 16; w++) tot += swarp[w];
            scount += tot;
        }
        __syncthreads();
    }
    if (tid == 0) g_supercount[blockIdx.x] = scount;
}

// ---------------------------------------------------------------------------
// Kernel 3: rasterizer, 16x8 px tiles, 1024 CTAs x 512 threads.
// CTA = (tile, half). 16 warps = 16 face slices; each thread owns 4 pixels:
// column x, rows y, y+2, y+4, y+6 (distances chained via d + 2Q).
// Chunked: cull 512 -> smem stage -> raster -> CTA-wide absorbing break.
// ---------------------------------------------------------------------------
__global__ __launch_bounds__(RT) void raster_kernel() {
    __shared__ float4 sfA[CHUNK], sfB[CHUNK], sfC[CHUNK];
    __shared__ float sprod[4][16][32];
    __shared__ int swarp[16];

    int tid  = threadIdx.x;
    int warp = tid >> 5, lane = tid & 31;
    int tix  = blockIdx.x & (NTILE - 1);
    int half = blockIdx.x >> 9;
    int bx = tix & 15, by = tix >> 4;          // 16 x 32 tiles of 16x8 px
    int stile = (by >> 2) * 8 + (bx >> 1);
    int supn = g_supercount[stile];

    float* prodout = g_prod + half * (RS * RS);

    int x  = bx * 16 + (lane & 15);
    int y0 = by * 8 + (lane >> 4);             // rows: y0, y0+2, y0+4, y0+6

    if (supn == 0) {                           // empty sky tile
        if (tid < 32) {
            int xx = bx * 16 + (tid & 15);
            int yy = by * 8 + (tid >> 4);
            #pragma unroll
            for (int r = 0; r < 4; r++)
                prodout[(yy + 2 * r) * RS + xx] = 1.f;
        }
        return;
    }

    int r0 = (supn * half) / NHALF;
    int r1 = (supn * (half + 1)) / NHALF;

    float tcx = (float)(bx * 16 + 8);
    float tcy = (float)(by * 8 + 4);

    float px = (float)x + 0.5f;
    float py = (float)y0 + 0.5f;

    const unsigned short* sup = g_superlist[stile];
    float p0 = 1.f, p1 = 1.f, p2 = 1.f, p3 = 1.f;
    const float KEXP = 2.8853900817779268f;    // 2 * log2(e)

    for (int cbase = r0; cbase < r1; cbase += CHUNK) {
        int cn = min(CHUNK, r1 - cbase);

        // ---- cull this chunk (one face per thread) ----
        bool keep = false;
        float4 E0, E1, E2;
        if (tid < cn) {
            int f = (int)sup[cbase + tid];
            E0 = g_face[f * 3 + 0];
            E1 = g_face[f * 3 + 1];
            E2 = g_face[f * 3 + 2];
            float m0 = fmaf(E0.x, tcx, fmaf(E0.y, tcy, E0.z)) + 7.5f * fabsf(E0.x) + 3.5f * fabsf(E0.y);
            float m1 = fmaf(E1.x, tcx, fmaf(E1.y, tcy, E1.z)) + 7.5f * fabsf(E1.x) + 3.5f * fabsf(E1.y);
            float m2 = fmaf(E2.x, tcx, fmaf(E2.y, tcy, E2.z)) + 7.5f * fabsf(E2.x) + 3.5f * fabsf(E2.y);
            keep = (m0 >= THRESH) && (m1 >= THRESH) && (m2 >= THRESH);
        }
        unsigned b = __ballot_sync(0xffffffffu, keep);
        if (lane == 0) swarp[warp] = __popc(b);
        __syncthreads();
        int base = 0, nlist = 0;
        #pragma unroll
        for (int w = 0; w < 16; w++) {
            int c = swarp[w];
            base  += (w < warp) ? c : 0;
            nlist += c;
        }
        if (keep) {
            int pos = base + __popc(b & ((1u << lane) - 1u));
            sfA[pos] = E0;
            sfB[pos] = E1;
            sfC[pos] = E2;
        }
        __syncthreads();

        // ---- raster this chunk's compacted faces, slice = warp ----
        int s0 = (nlist * warp) >> 4;
        int s1 = (nlist * (warp + 1)) >> 4;
        for (int i = s0; i < s1; i++) {
            float4 F0 = sfA[i], F1 = sfB[i], F2 = sfC[i];
            float a0 = fmaf(F0.y, py, fmaf(F0.x, px, F0.z));
            float a1 = fmaf(F1.y, py, fmaf(F1.x, px, F1.z));
            float a2 = fmaf(F2.y, py, fmaf(F2.x, px, F2.z));
            float q0 = 2.f * F0.y, q1 = 2.f * F1.y, q2 = 2.f * F2.y;
            float b0 = a0 + q0, b1 = a1 + q1, b2 = a2 + q2;
            float c0 = b0 + q0, c1 = b1 + q1, c2 = b2 + q2;
            float e0 = c0 + q0, e1 = c1 + q1, e2 = c2 + q2;
            float m0 = fminf(a0, fminf(a1, a2));
            float m1 = fminf(b0, fminf(b1, b2));
            float m2 = fminf(c0, fminf(c1, c2));
            float m3 = fminf(e0, fminf(e1, e2));
            bool act0 = (m0 > THRESH) && (p0 != 0.f);
            bool act1 = (m1 > THRESH) && (p1 != 0.f);
            bool act2 = (m2 > THRESH) && (p2 != 0.f);
            bool act3 = (m3 > THRESH) && (p3 != 0.f);
            if (__any_sync(0xffffffffu, act0 || act1 || act2 || act3)) {
                if (act0) {
                    float t, rc;
                    asm("ex2.approx.ftz.f32 %0, %1;" : "=f"(t) : "f"(m0 * KEXP));
                    asm("rcp.approx.ftz.f32 %0, %1;" : "=f"(rc) : "f"(1.f + t));
                    p0 *= fmaxf(rc, 1e-6f);
                }
                if (act1) {
                    float t, rc;
                    asm("ex2.approx.ftz.f32 %0, %1;" : "=f"(t) : "f"(m1 * KEXP));
                    asm("rcp.approx.ftz.f32 %0, %1;" : "=f"(rc) : "f"(1.f + t));
                    p1 *= fmaxf(rc, 1e-6f);
                }
                if (act2) {
                    float t, rc;
                    asm("ex2.approx.ftz.f32 %0, %1;" : "=f"(t) : "f"(m2 * KEXP));
                    asm("rcp.approx.ftz.f32 %0, %1;" : "=f"(rc) : "f"(1.f + t));
                    p2 *= fmaxf(rc, 1e-6f);
                }
                if (act3) {
                    float t, rc;
                    asm("ex2.approx.ftz.f32 %0, %1;" : "=f"(t) : "f"(m3 * KEXP));
                    asm("rcp.approx.ftz.f32 %0, %1;" : "=f"(rc) : "f"(1.f + t));
                    p3 *= fmaxf(rc, 1e-6f);
                }
            }
            if (((i & 7) == 7) &&
                __all_sync(0xffffffffu,
                           (p0 == 0.f) && (p1 == 0.f) && (p2 == 0.f) && (p3 == 0.f)))
                break;
        }

        // ---- CTA-wide absorbing-zero break ----
        bool wz = __all_sync(0xffffffffu,
                             (p0 == 0.f) && (p1 == 0.f) && (p2 == 0.f) && (p3 == 0.f));
        if (lane == 0) swarp[warp] = wz ? 1 : 0;
        __syncthreads();
        int alldead = 1;
        #pragma unroll
        for (int w = 0; w < 16; w++) alldead &= swarp[w];
        __syncthreads();   // protect swarp reuse next chunk
        if (alldead) break;
    }
    sprod[0][warp][lane] = p0;
    sprod[1][warp][lane] = p1;
    sprod[2][warp][lane] = p2;
    sprod[3][warp][lane] = p3;
    __syncthreads();

    // ---- combine 16 slice partials per pixel in ascending slice order ----
    if (tid < 32) {
        int xx = bx * 16 + (tid & 15);
        int yy = by * 8 + (tid >> 4);
        #pragma unroll
        for (int r = 0; r < 4; r++) {
            float p = sprod[r][0][tid];
            #pragma unroll
            for (int s = 1; s < 16; s++) p *= sprod[r][s][tid];
            prodout[(yy + 2 * r) * RS + xx] = p;
        }
    }
}

// ---------------------------------------------------------------------------
// Kernel 4: combine halves, nearest upsample 256->640, crop, si, partial SSE
// 4 consecutive pixels per thread; float4 mask load, SCALAR out stores
// (out + si_offset is only 4-byte aligned when si_offset=1).
// ---------------------------------------------------------------------------
__global__ __launch_bounds__(256) void finalize_kernel(const float* __restrict__ mask,
                                                       float* __restrict__ out,
                                                       int si_offset) {
    int idx = (blockIdx.x * 256 + threadIdx.x) * 4;
    int r = idx / IMGW;
    int c = idx - r * IMGW;
    int sr = (2 * r + 1) / 5;
    const float* prow0 = g_prod + sr * RS;
    const float* prow1 = g_prod + RS * RS + sr * RS;
    float4 m4 = *reinterpret_cast<const float4*>(mask + idx);
    float sq = 0.f;
    float si4[4];
    #pragma unroll
    for (int k = 0; k < 4; k++) {
        int sc = (2 * (c + k) + 1) / 5;
        float si = 1.f - prow0[sc] * prow1[sc];
        si4[k] = si;
        float d = si - ((const float*)&m4)[k];
        sq += d * d;
    }
    #pragma unroll
    for (int k = 0; k < 4; k++)
        out[idx + si_offset + k] = si4[k];

    __shared__ float red[8];
    #pragma unroll
    for (int o = 16; o > 0; o >>= 1)
        sq += __shfl_down_sync(0xffffffffu, sq, o);
    int warp = threadIdx.x >> 5, lane = threadIdx.x & 31;
    if (lane == 0) red[warp] = sq;
    __syncthreads();
    if (threadIdx.x == 0) {
        float s = 0.f;
        #pragma unroll
        for (int w = 0; w < 8; w++) s += red[w];
        g_partial[blockIdx.x] = s;
    }
}

__global__ __launch_bounds__(256) void loss_kernel(float* __restrict__ out) {
    int tid = threadIdx.x;
    float s = 0.f;
    for (int i = tid; i < FBLK; i += 256) s += g_partial[i];
    __shared__ float red[256];
    red[tid] = s;
    __syncthreads();
    #pragma unroll
    for (int o = 128; o > 0; o >>= 1) {
        if (tid < o) red[tid] += red[tid + o];
        __syncthreads();
    }
    if (tid == 0) out[0] = red[0];
}

// ---------------------------------------------------------------------------
extern "C" void kernel_launch(void* const* d_in, const int* in_sizes, int n_in,
                              void* d_out, int out_size) {
    const float* dof   = (const float*)d_in[0];
    const float* verts = (const float*)d_in[1];
    const int*   faces = (const int*)d_in[2];
    const float* K     = (const float*)d_in[3];
    const float* mask  = (const float*)d_in[4];
    float* out = (float*)d_out;

    int has_loss = (out_size >= NPIX + 1) ? 1 : 0;

    setup_face_kernel<<<4, 512>>>(dof, verts, K, faces);
    supercull_kernel<<<NSUPER, 512>>>();
    raster_kernel<<<NTILE * NHALF, RT>>>();
    finalize_kernel<<<FBLK, 256>>>(mask, out, has_loss);
    if (has_loss) loss_kernel<<<1, 256>>>(out);
}

// round 11
// speedup vs baseline: 4.8429x; 1.2000x over previous
#include <cuda_runtime.h>
#include <cstdint>

#define RS 256
#define NV 2048
#define NF 4096
#define IMGH 480
#define IMGW 640
#define NPIX (IMGH * IMGW)
#define FBLK (NPIX / 1024)   // finalize blocks (4 px/thread)
#define THRESH (-8.5f)       // exact: dmin < -8.5 -> factor == 1.0f bitwise
#define NSUPER 64            // 8x8 super-tiles of 32x32 px
#define RT 512               // raster CTA threads
#define CHUNK 512            // faces per cull/raster round
#define NHALF 2              // face-range splits per tile
#define NTILE 512            // 16x8-px tiles: 16 x 32

__device__ float4 g_face[NF * 3];
__device__ float  g_prod[NHALF * RS * RS];
__device__ unsigned long long g_loss_fx;
__device__ unsigned int g_done;
__device__ unsigned short g_superlist[NSUPER][NF];
__device__ int    g_supercount[NSUPER];

// ---------------------------------------------------------------------------
// Kernel 1: fused se3_exp + vertex transform + projection + face coefficients
// 4 CTAs: each redundantly transforms verts (cheap), builds NF/4 faces.
// CTA 0 also zeroes the loss accumulators (stream-ordered before finalize).
// ---------------------------------------------------------------------------
__global__ __launch_bounds__(512) void setup_face_kernel(
        const float* __restrict__ dof,
        const float* __restrict__ verts,
        const float* __restrict__ Kin,
        const int*   __restrict__ faces) {
    __shared__ float2 sxy[NV];
    __shared__ float sR[9], sT[3], sK[9];
    int tid = threadIdx.x;
    if (blockIdx.x == 0 && tid == 1) { g_loss_fx = 0ull; g_done = 0u; }
    if (tid == 0) {
        float v0 = dof[0], v1 = dof[1], v2 = dof[2];
        float w0 = dof[3], w1 = dof[4], w2 = dof[5];
        float th2 = w0 * w0 + w1 * w1 + w2 * w2;
        float th  = sqrtf(th2 + 1e-30f);
        bool small = th < 1e-4f;
        float th_s  = small ? 1.f : th;
        float th2_s = small ? 1.f : th2;
        float A = small ? (1.f - th2 / 6.f)   : (sinf(th_s) / th_s);
        float B = small ? (0.5f - th2 / 24.f) : ((1.f - cosf(th_s)) / th2_s);
        float C = small ? (1.f / 6.f - th2 / 120.f)
                        : ((th_s - sinf(th_s)) / (th2_s * th_s));
        float Kx[9] = {0.f, -w2,  w1,
                       w2,  0.f, -w0,
                      -w1,  w0,  0.f};
        float K2[9];
        #pragma unroll
        for (int r = 0; r < 3; r++)
            #pragma unroll
            for (int c = 0; c < 3; c++) {
                float acc = 0.f;
                #pragma unroll
                for (int k = 0; k < 3; k++) acc += Kx[r * 3 + k] * Kx[k * 3 + c];
                K2[r * 3 + c] = acc;
            }
        float V[9];
        #pragma unroll
        for (int i = 0; i < 9; i++) {
            float I = (i == 0 || i == 4 || i == 8) ? 1.f : 0.f;
            sR[i] = I + A * Kx[i] + B * K2[i];
            V[i]  = I + B * Kx[i] + C * K2[i];
        }
        sT[0] = V[0] * v0 + V[1] * v1 + V[2] * v2;
        sT[1] = V[3] * v0 + V[4] * v1 + V[5] * v2;
        sT[2] = V[6] * v0 + V[7] * v1 + V[8] * v2;
    }
    if (tid < 9) sK[tid] = Kin[tid];
    __syncthreads();
    for (int i = tid; i < NV; i += 512) {
        float x = verts[3 * i + 0], y = verts[3 * i + 1], z = verts[3 * i + 2];
        float cx = sR[0] * x + sR[1] * y + sR[2] * z + sT[0];
        float cy = sR[3] * x + sR[4] * y + sR[5] * z + sT[1];
        float cz = sR[6] * x + sR[7] * y + sR[8] * z + sT[2];
        float u = sK[0] * cx + sK[1] * cy + sK[2] * cz;
        float v = sK[3] * cx + sK[4] * cy + sK[5] * cz;
        float w = sK[6] * cx + sK[7] * cy + sK[8] * cz;
        sxy[i] = make_float2((u / w) * 0.4f, (v / w) * 0.4f);
    }
    __syncthreads();
    int fbase = blockIdx.x * (NF / 4);
    for (int f = fbase + tid; f < fbase + NF / 4; f += 512) {
        int i0 = faces[3 * f + 0];
        int i1 = faces[3 * f + 1];
        int i2 = faces[3 * f + 2];
        float2 p0 = sxy[i0], p1 = sxy[i1], p2 = sxy[i2];
        float2 e[3];
        e[0] = make_float2(p1.x - p0.x, p1.y - p0.y);
        e[1] = make_float2(p2.x - p1.x, p2.y - p1.y);
        e[2] = make_float2(p0.x - p2.x, p0.y - p2.y);
        float2 a[3] = {p0, p1, p2};
        float area2 = e[0].y * e[2].x - e[0].x * e[2].y;
        float sgn = (area2 >= 0.f) ? 1.f : -1.f;
        #pragma unroll
        for (int k = 0; k < 3; k++) {
            float elen = sqrtf(e[k].x * e[k].x + e[k].y * e[k].y) + 1e-9f;
            float s = sgn / elen;
            float c0 = e[k].x * a[k].y - e[k].y * a[k].x;
            g_face[f * 3 + k] = make_float4(-s * e[k].y, s * e[k].x, -s * c0, 0.f);
        }
    }
}

// ---------------------------------------------------------------------------
// Kernel 2: super-tile cull (32x32 px), ordered compaction, 512 threads.
// ---------------------------------------------------------------------------
__global__ __launch_bounds__(512) void supercull_kernel() {
    __shared__ int swarp[16];
    __shared__ int scount;
    int tid  = threadIdx.x;
    int warp = tid >> 5, lane = tid & 31;
    int sx = blockIdx.x & 7, sy = blockIdx.x >> 3;
    float tcx = (float)(sx * 32 + 16);
    float tcy = (float)(sy * 32 + 16);

    if (tid == 0) scount = 0;
    __syncthreads();

    for (int r = 0; r < NF / 512; r++) {
        int f = r * 512 + tid;
        float4 E0 = g_face[f * 3 + 0];
        float4 E1 = g_face[f * 3 + 1];
        float4 E2 = g_face[f * 3 + 2];
        float m0 = fmaf(E0.x, tcx, fmaf(E0.y, tcy, E0.z)) + 15.5f * (fabsf(E0.x) + fabsf(E0.y));
        float m1 = fmaf(E1.x, tcx, fmaf(E1.y, tcy, E1.z)) + 15.5f * (fabsf(E1.x) + fabsf(E1.y));
        float m2 = fmaf(E2.x, tcx, fmaf(E2.y, tcy, E2.z)) + 15.5f * (fabsf(E2.x) + fabsf(E2.y));
        bool keep = (m0 >= THRESH) && (m1 >= THRESH) && (m2 >= THRESH);

        unsigned b = __ballot_sync(0xffffffffu, keep);
        if (lane == 0) swarp[warp] = __popc(b);
        __syncthreads();
        int base = scount;
        #pragma unroll
        for (int w = 0; w < 16; w++) base += (w < warp) ? swarp[w] : 0;
        if (keep)
            g_superlist[blockIdx.x][base + __popc(b & ((1u << lane) - 1u))] = (unsigned short)f;
        __syncthreads();
        if (tid == 0) {
            int tot = 0;
            #pragma unroll
            for (int w = 0; w < 16; w++) tot += swarp[w];
            scount += tot;
        }
        __syncthreads();
    }
    if (tid == 0) g_supercount[blockIdx.x] = scount;
}

// ---------------------------------------------------------------------------
// Kernel 3: rasterizer, 16x8 px tiles, 1024 CTAs x 512 threads.
// Branch-free inner loop: den *= (1 + ex2(dmin*K)) per row per face; faces
// with dmin < -8.5 contribute exactly 1.0f. Flush p *= rcp(den) every 8 faces.
// ---------------------------------------------------------------------------
__global__ __launch_bounds__(RT) void raster_kernel() {
    __shared__ float4 sfA[CHUNK], sfB[CHUNK], sfC[CHUNK];
    __shared__ float sprod[4][16][32];
    __shared__ int swarp[16];

    int tid  = threadIdx.x;
    int warp = tid >> 5, lane = tid & 31;
    int tix  = blockIdx.x & (NTILE - 1);
    int half = blockIdx.x >> 9;
    int bx = tix & 15, by = tix >> 4;          // 16 x 32 tiles of 16x8 px
    int stile = (by >> 2) * 8 + (bx >> 1);
    int supn = g_supercount[stile];

    float* prodout = g_prod + half * (RS * RS);

    int x  = bx * 16 + (lane & 15);
    int y0 = by * 8 + (lane >> 4);             // rows: y0, y0+2, y0+4, y0+6

    if (supn == 0) {                           // empty sky tile
        if (tid < 32) {
            int xx = bx * 16 + (tid & 15);
            int yy = by * 8 + (tid >> 4);
            #pragma unroll
            for (int r = 0; r < 4; r++)
                prodout[(yy + 2 * r) * RS + xx] = 1.f;
        }
        return;
    }

    int r0 = (supn * half) / NHALF;
    int r1 = (supn * (half + 1)) / NHALF;

    float tcx = (float)(bx * 16 + 8);
    float tcy = (float)(by * 8 + 4);

    float px = (float)x + 0.5f;
    float py = (float)y0 + 0.5f;

    const unsigned short* sup = g_superlist[stile];
    float p0 = 1.f, p1 = 1.f, p2 = 1.f, p3 = 1.f;
    const float KEXP = 2.8853900817779268f;    // 2 * log2(e)

    for (int cbase = r0; cbase < r1; cbase += CHUNK) {
        int cn = min(CHUNK, r1 - cbase);

        // ---- cull this chunk (one face per thread) ----
        bool keep = false;
        float4 E0, E1, E2;
        if (tid < cn) {
            int f = (int)sup[cbase + tid];
            E0 = g_face[f * 3 + 0];
            E1 = g_face[f * 3 + 1];
            E2 = g_face[f * 3 + 2];
            float m0 = fmaf(E0.x, tcx, fmaf(E0.y, tcy, E0.z)) + 7.5f * fabsf(E0.x) + 3.5f * fabsf(E0.y);
            float m1 = fmaf(E1.x, tcx, fmaf(E1.y, tcy, E1.z)) + 7.5f * fabsf(E1.x) + 3.5f * fabsf(E1.y);
            float m2 = fmaf(E2.x, tcx, fmaf(E2.y, tcy, E2.z)) + 7.5f * fabsf(E2.x) + 3.5f * fabsf(E2.y);
            keep = (m0 >= THRESH) && (m1 >= THRESH) && (m2 >= THRESH);
        }
        unsigned b = __ballot_sync(0xffffffffu, keep);
        if (lane == 0) swarp[warp] = __popc(b);
        __syncthreads();
        int base = 0, nlist = 0;
        #pragma unroll
        for (int w = 0; w < 16; w++) {
            int c = swarp[w];
            base  += (w < warp) ? c : 0;
            nlist += c;
        }
        if (keep) {
            int pos = base + __popc(b & ((1u << lane) - 1u));
            sfA[pos] = E0;
            sfB[pos] = E1;
            sfC[pos] = E2;
        }
        __syncthreads();

        // ---- raster this chunk's compacted faces, slice = warp ----
        int s0 = (nlist * warp) >> 4;
        int s1 = (nlist * (warp + 1)) >> 4;
        float den0 = 1.f, den1 = 1.f, den2 = 1.f, den3 = 1.f;
        for (int i = s0; i < s1; i++) {
            float4 F0 = sfA[i], F1 = sfB[i], F2 = sfC[i];
            float a0 = fmaf(F0.y, py, fmaf(F0.x, px, F0.z));
            float a1 = fmaf(F1.y, py, fmaf(F1.x, px, F1.z));
            float a2 = fmaf(F2.y, py, fmaf(F2.x, px, F2.z));
            float q0 = F0.y + F0.y, q1 = F1.y + F1.y, q2 = F2.y + F2.y;
            float b0 = a0 + q0, b1 = a1 + q1, b2 = a2 + q2;
            float c0 = b0 + q0, c1 = b1 + q1, c2 = b2 + q2;
            float e0 = c0 + q0, e1 = c1 + q1, e2 = c2 + q2;
            float m0 = fminf(a0, fminf(a1, a2));
            float m1 = fminf(b0, fminf(b1, b2));
            float m2 = fminf(c0, fminf(c1, c2));
            float m3 = fminf(e0, fminf(e1, e2));
            float t0, t1, t2, t3;
            asm("ex2.approx.ftz.f32 %0, %1;" : "=f"(t0) : "f"(m0 * KEXP));
            asm("ex2.approx.ftz.f32 %0, %1;" : "=f"(t1) : "f"(m1 * KEXP));
            asm("ex2.approx.ftz.f32 %0, %1;" : "=f"(t2) : "f"(m2 * KEXP));
            asm("ex2.approx.ftz.f32 %0, %1;" : "=f"(t3) : "f"(m3 * KEXP));
            den0 *= (1.f + t0);
            den1 *= (1.f + t1);
            den2 *= (1.f + t2);
            den3 *= (1.f + t3);
            if (((i & 7) == 7) || (i == s1 - 1)) {   // flush batch
                float r0f, r1f, r2f, r3f;
                asm("rcp.approx.ftz.f32 %0, %1;" : "=f"(r0f) : "f"(den0));
                asm("rcp.approx.ftz.f32 %0, %1;" : "=f"(r1f) : "f"(den1));
                asm("rcp.approx.ftz.f32 %0, %1;" : "=f"(r2f) : "f"(den2));
                asm("rcp.approx.ftz.f32 %0, %1;" : "=f"(r3f) : "f"(den3));
                p0 *= r0f; p1 *= r1f; p2 *= r2f; p3 *= r3f;
                den0 = den1 = den2 = den3 = 1.f;
                if (__all_sync(0xffffffffu,
                               (p0 == 0.f) && (p1 == 0.f) && (p2 == 0.f) && (p3 == 0.f)))
                    break;
            }
        }

        // ---- CTA-wide absorbing-zero break ----
        bool wz = __all_sync(0xffffffffu,
                             (p0 == 0.f) && (p1 == 0.f) && (p2 == 0.f) && (p3 == 0.f));
        if (lane == 0) swarp[warp] = wz ? 1 : 0;
        __syncthreads();
        int alldead = 1;
        #pragma unroll
        for (int w = 0; w < 16; w++) alldead &= swarp[w];
        __syncthreads();   // protect swarp reuse next chunk
        if (alldead) break;
    }
    sprod[0][warp][lane] = p0;
    sprod[1][warp][lane] = p1;
    sprod[2][warp][lane] = p2;
    sprod[3][warp][lane] = p3;
    __syncthreads();

    // ---- combine 16 slice partials per pixel in ascending slice order ----
    if (tid < 32) {
        int xx = bx * 16 + (tid & 15);
        int yy = by * 8 + (tid >> 4);
        #pragma unroll
        for (int r = 0; r < 4; r++) {
            float p = sprod[r][0][tid];
            #pragma unroll
            for (int s = 1; s < 16; s++) p *= sprod[r][s][tid];
            prodout[(yy + 2 * r) * RS + xx] = p;
        }
    }
}

// ---------------------------------------------------------------------------
// Kernel 4: combine halves, upsample, crop, si, SSE; loss fused via
// fixed-point (x2^32) atomicAdd (order-independent -> deterministic);
// last block converts and writes out[0].
// ---------------------------------------------------------------------------
__global__ __launch_bounds__(256) void finalize_kernel(const float* __restrict__ mask,
                                                       float* __restrict__ out,
                                                       int si_offset) {
    int idx = (blockIdx.x * 256 + threadIdx.x) * 4;
    int r = idx / IMGW;
    int c = idx - r * IMGW;
    int sr = (2 * r + 1) / 5;
    const float* prow0 = g_prod + sr * RS;
    const float* prow1 = g_prod + RS * RS + sr * RS;
    float4 m4 = *reinterpret_cast<const float4*>(mask + idx);
    float sq = 0.f;
    float si4[4];
    #pragma unroll
    for (int k = 0; k < 4; k++) {
        int sc = (2 * (c + k) + 1) / 5;
        float si = 1.f - prow0[sc] * prow1[sc];
        si4[k] = si;
        float d = si - ((const float*)&m4)[k];
        sq += d * d;
    }
    #pragma unroll
    for (int k = 0; k < 4; k++)
        out[idx + si_offset + k] = si4[k];

    if (!si_offset) return;   // no loss slot in output

    __shared__ float red[8];
    #pragma unroll
    for (int o = 16; o > 0; o >>= 1)
        sq += __shfl_down_sync(0xffffffffu, sq, o);
    int warp = threadIdx.x >> 5, lane = threadIdx.x & 31;
    if (lane == 0) red[warp] = sq;
    __syncthreads();
    if (threadIdx.x == 0) {
        float s = 0.f;
        #pragma unroll
        for (int w = 0; w < 8; w++) s += red[w];
        // fixed-point accumulate: block sum <= 1024, scale 2^32 -> fits u64
        unsigned long long fx = (unsigned long long)((double)s * 4294967296.0);
        atomicAdd(&g_loss_fx, fx);
        __threadfence();
        unsigned int done = atomicAdd(&g_done, 1u);
        if (done == FBLK - 1) {
            double total = (double)g_loss_fx * (1.0 / 4294967296.0);
            out[0] = (float)total;
        }
    }
}

// ---------------------------------------------------------------------------
extern "C" void kernel_launch(void* const* d_in, const int* in_sizes, int n_in,
                              void* d_out, int out_size) {
    const float* dof   = (const float*)d_in[0];
    const float* verts = (const float*)d_in[1];
    const int*   faces = (const int*)d_in[2];
    const float* K     = (const float*)d_in[3];
    const float* mask  = (const float*)d_in[4];
    float* out = (float*)d_out;

    int has_loss = (out_size >= NPIX + 1) ? 1 : 0;

    setup_face_kernel<<<4, 512>>>(dof, verts, K, faces);
    supercull_kernel<<<NSUPER, 512>>>();
    raster_kernel<<<NTILE * NHALF, RT>>>();
    finalize_kernel<<<FBLK, 256>>>(mask, out, has_loss);
}